// round 1
// baseline (speedup 1.0000x reference)
#include <cuda_runtime.h>
#include <math.h>

// ---- problem constants ----
#define N_TOK   512
#define QDIM    64
#define H_HEADS 4
#define D_HEAD  128
#define HD      512            // H*D
#define BD      128
#define HBD     512            // H*BD
#define NN      (N_TOK * N_TOK)    // 262144 pairs
#define INV_SQRT_D 0.08838834764831845f   // 1/sqrt(128)

// ---- scratch (static device globals; no allocations allowed) ----
__device__ float g_pq[N_TOK * HD];        // [n][h*128+d]
__device__ float g_pk[N_TOK * HD];
__device__ float g_diffs[H_HEADS * NN];   // [h][q*512+k]
__device__ float g_logits[H_HEADS * NN];
__device__ float g_val[H_HEADS * N_TOK];

__device__ __forceinline__ float mishf(float x) {
    float sp = (x > 20.f) ? x : log1pf(expf(x));
    return x * tanhf(sp);
}

// =====================================================================
// Kernel 1: q/k projections  pq[n, h*128+d] = q[n,:] @ Wq[h*128+d,:] + bq
// grid (512, 2), 256 threads
// =====================================================================
__global__ void __launch_bounds__(256) proj_kernel(
    const float* __restrict__ q,  const float* __restrict__ Wq, const float* __restrict__ bq,
    const float* __restrict__ k,  const float* __restrict__ Wk, const float* __restrict__ bk)
{
    const float* x; const float* W; const float* b; float* out;
    if (blockIdx.y == 0) { x = q; W = Wq; b = bq; out = g_pq; }
    else                 { x = k; W = Wk; b = bk; out = g_pk; }
    int n = blockIdx.x;
    int t = threadIdx.x;
    __shared__ float xs[QDIM];
    if (t < QDIM/4) ((float4*)xs)[t] = ((const float4*)(x + n * QDIM))[t];
    __syncthreads();
    for (int j = t; j < HD; j += 256) {
        float s = b[j];
        const float4* wr = (const float4*)(W + j * QDIM);
        #pragma unroll
        for (int c = 0; c < QDIM/4; c++) {
            float4 w = wr[c];
            s += xs[4*c+0]*w.x + xs[4*c+1]*w.y + xs[4*c+2]*w.z + xs[4*c+3]*w.w;
        }
        out[n * HD + j] = s;
    }
}

// =====================================================================
// Kernel 2 (THE BIG ONE): fused bias pipeline.
// Per CTA: 32 pair-rows.
//   P[32,512] = bias_tile @ Wb^T + bb          (kept in SMEM)
//   diffs[h,m] = ||P[m, h*128 .. +128]||_2
//   bias_out[m,:] = mish(P @ Wbo^T + bbo)
// grid 8192, 256 threads, ~113KB dyn smem
// =====================================================================
#define ROWS 32
#define PS_PITCH 516
#define W1_PITCH 129
#define W2_PITCH 65
#define WS_FLOATS 8320   // max(64*129=8256, 128*65=8320)

__global__ void __launch_bounds__(256) bias_fused_kernel(
    const float* __restrict__ bias, const float* __restrict__ Wb,
    const float* __restrict__ bb,   const float* __restrict__ Wbo,
    const float* __restrict__ bbo,  float* __restrict__ bias_out)
{
    extern __shared__ float sm[];
    float* Bs = sm;                        // [32][128]
    float* Ps = Bs + ROWS * BD;            // [32][516]
    float* Ws = Ps + ROWS * PS_PITCH;      // WS_FLOATS

    int m0 = blockIdx.x * ROWS;
    int t  = threadIdx.x;
    int ty = t >> 5;   // 0..7
    int tx = t & 31;   // 0..31

    // load bias tile (32x128 floats = 1024 float4)
    {
        const float4* gb = (const float4*)(bias + (size_t)m0 * BD);
        float4* Bs4 = (float4*)Bs;
        #pragma unroll
        for (int i = t; i < ROWS * BD / 4; i += 256) Bs4[i] = gb[i];
    }
    __syncthreads();

    // ---------------- GEMM1: P = B @ Wb^T + bb ----------------
    for (int nc = 0; nc < HBD; nc += 64) {
        // load Wb rows [nc, nc+64) x 128 into Ws, pitch 129
        #pragma unroll
        for (int i = t; i < 64 * 32; i += 256) {
            int r  = i >> 5;
            int c4 = i & 31;
            float4 w = ((const float4*)Wb)[(nc + r) * 32 + c4];
            float* dst = Ws + r * W1_PITCH + c4 * 4;
            dst[0] = w.x; dst[1] = w.y; dst[2] = w.z; dst[3] = w.w;
        }
        __syncthreads();

        float a00=0,a01=0,a10=0,a11=0,a20=0,a21=0,a30=0,a31=0;
        const float* bp = Bs + (ty * 4) * BD;
        const float* w0p = Ws + tx * W1_PITCH;
        const float* w1p = Ws + (tx + 32) * W1_PITCH;
        #pragma unroll 8
        for (int kk = 0; kk < BD; kk++) {
            float b0 = bp[kk], b1 = bp[BD + kk], b2 = bp[2*BD + kk], b3 = bp[3*BD + kk];
            float w0 = w0p[kk], w1 = w1p[kk];
            a00 += b0*w0; a01 += b0*w1;
            a10 += b1*w0; a11 += b1*w1;
            a20 += b2*w0; a21 += b2*w1;
            a30 += b3*w0; a31 += b3*w1;
        }
        float bb0 = bb[nc + tx], bb1 = bb[nc + tx + 32];
        int rbase = (ty * 4) * PS_PITCH + nc + tx;
        Ps[rbase              ] = a00 + bb0;  Ps[rbase + 32             ] = a01 + bb1;
        Ps[rbase + PS_PITCH   ] = a10 + bb0;  Ps[rbase + PS_PITCH + 32  ] = a11 + bb1;
        Ps[rbase + 2*PS_PITCH ] = a20 + bb0;  Ps[rbase + 2*PS_PITCH + 32] = a21 + bb1;
        Ps[rbase + 3*PS_PITCH ] = a30 + bb0;  Ps[rbase + 3*PS_PITCH + 32] = a31 + bb1;
        __syncthreads();
    }

    // ---------------- per-head norms -> g_diffs ----------------
    if (t < 128) {
        int row = t >> 2;
        int h   = t & 3;
        const float* pr = Ps + row * PS_PITCH + h * BD;
        float s = 0.f;
        #pragma unroll 8
        for (int c = 0; c < BD; c++) { float p = pr[c]; s += p * p; }
        g_diffs[h * NN + (m0 + row)] = sqrtf(s);
    }

    // ---------------- GEMM2: O = P @ Wbo^T + bbo, mish ----------------
    float acc[4][4];
    #pragma unroll
    for (int i = 0; i < 4; i++)
        #pragma unroll
        for (int j = 0; j < 4; j++) acc[i][j] = 0.f;

    for (int nc = 0; nc < HBD; nc += 64) {
        __syncthreads();   // protect Ws from previous readers
        // load Wbo[0..128) x cols [nc, nc+64) into Ws, pitch 65
        #pragma unroll
        for (int i = t; i < 128 * 16; i += 256) {
            int o  = i >> 4;
            int c4 = i & 15;
            float4 w = ((const float4*)Wbo)[o * 128 + (nc >> 2) + c4];
            float* dst = Ws + o * W2_PITCH + c4 * 4;
            dst[0] = w.x; dst[1] = w.y; dst[2] = w.z; dst[3] = w.w;
        }
        __syncthreads();

        const float* pp = Ps + (ty * 4) * PS_PITCH + nc;
        #pragma unroll 4
        for (int kk = 0; kk < 64; kk++) {
            float p0 = pp[kk], p1 = pp[PS_PITCH + kk], p2 = pp[2*PS_PITCH + kk], p3 = pp[3*PS_PITCH + kk];
            float w0 = Ws[(tx     ) * W2_PITCH + kk];
            float w1 = Ws[(tx + 32) * W2_PITCH + kk];
            float w2 = Ws[(tx + 64) * W2_PITCH + kk];
            float w3 = Ws[(tx + 96) * W2_PITCH + kk];
            acc[0][0] += p0*w0; acc[0][1] += p0*w1; acc[0][2] += p0*w2; acc[0][3] += p0*w3;
            acc[1][0] += p1*w0; acc[1][1] += p1*w1; acc[1][2] += p1*w2; acc[1][3] += p1*w3;
            acc[2][0] += p2*w0; acc[2][1] += p2*w1; acc[2][2] += p2*w2; acc[2][3] += p2*w3;
            acc[3][0] += p3*w0; acc[3][1] += p3*w1; acc[3][2] += p3*w2; acc[3][3] += p3*w3;
        }
    }

    #pragma unroll
    for (int i = 0; i < 4; i++) {
        int row = ty * 4 + i;
        #pragma unroll
        for (int j = 0; j < 4; j++) {
            int o = tx + 32 * j;
            float x = acc[i][j] + bbo[o];
            bias_out[(size_t)(m0 + row) * BD + o] = mishf(x);
        }
    }
}

// =====================================================================
// Kernel 3: logits[h,q,k] = (pq[q,h,:] . pk[k,h,:]) / sqrt(D) + diffs[h,q,k]
// grid (32, 4) : (q-tile of 16, head), 256 threads
// =====================================================================
__global__ void __launch_bounds__(256) logits_kernel()
{
    __shared__ float pq_s[16 * 128];
    __shared__ float pk_s[64 * 129];
    int q0 = blockIdx.x * 16;
    int h  = blockIdx.y;
    int t  = threadIdx.x;
    int qi = t >> 4;    // 0..15
    int kx = t & 15;    // 0..15

    // load pq tile [16][128]
    #pragma unroll
    for (int i = t; i < 16 * 32; i += 256) {
        int r = i >> 5, c4 = i & 31;
        ((float4*)pq_s)[r * 32 + c4] = ((const float4*)g_pq)[(q0 + r) * 128 + h * 32 + c4];
    }

    for (int kc = 0; kc < 8; kc++) {
        __syncthreads();
        // load pk chunk [64][128], pitch 129
        #pragma unroll
        for (int i = t; i < 64 * 32; i += 256) {
            int r = i >> 5, c4 = i & 31;
            float4 w = ((const float4*)g_pk)[(kc * 64 + r) * 128 + h * 32 + c4];
            float* dst = pk_s + r * 129 + c4 * 4;
            dst[0] = w.x; dst[1] = w.y; dst[2] = w.z; dst[3] = w.w;
        }
        __syncthreads();

        float acc0 = 0, acc1 = 0, acc2 = 0, acc3 = 0;
        const float* ap = pq_s + qi * 128;
        const float* k0 = pk_s + (kx * 4    ) * 129;
        const float* k1 = pk_s + (kx * 4 + 1) * 129;
        const float* k2 = pk_s + (kx * 4 + 2) * 129;
        const float* k3 = pk_s + (kx * 4 + 3) * 129;
        #pragma unroll 8
        for (int d = 0; d < 128; d++) {
            float a = ap[d];
            acc0 += a * k0[d]; acc1 += a * k1[d];
            acc2 += a * k2[d]; acc3 += a * k3[d];
        }
        size_t base = (size_t)h * NN + (size_t)(q0 + qi) * N_TOK + kc * 64 + kx * 4;
        float4 dsum = *(const float4*)(g_diffs + base);
        float4 o;
        o.x = acc0 * INV_SQRT_D + dsum.x;
        o.y = acc1 * INV_SQRT_D + dsum.y;
        o.z = acc2 * INV_SQRT_D + dsum.z;
        o.w = acc3 * INV_SQRT_D + dsum.w;
        *(float4*)(g_logits + base) = o;
    }
}

// =====================================================================
// Kernel 4: softmax over k, dot with v -> g_val[h*512+q]
// grid 2048, 256 threads
// =====================================================================
__global__ void __launch_bounds__(256) softmax_v_kernel(const float* __restrict__ v)
{
    __shared__ float r1[256];
    __shared__ float r2[256];
    int hq = blockIdx.x;
    int t  = threadIdx.x;
    const float* lr = g_logits + (size_t)hq * N_TOK;
    float l0 = lr[t], l1 = lr[t + 256];
    float m = fmaxf(l0, l1);
    r1[t] = m;
    __syncthreads();
    #pragma unroll
    for (int s = 128; s > 0; s >>= 1) {
        if (t < s) r1[t] = fmaxf(r1[t], r1[t + s]);
        __syncthreads();
    }
    m = r1[0];
    __syncthreads();
    float e0 = expf(l0 - m), e1 = expf(l1 - m);
    r1[t] = e0 + e1;
    r2[t] = e0 * v[t] + e1 * v[t + 256];
    __syncthreads();
    #pragma unroll
    for (int s = 128; s > 0; s >>= 1) {
        if (t < s) { r1[t] += r1[t + s]; r2[t] += r2[t + s]; }
        __syncthreads();
    }
    if (t == 0) g_val[hq] = r2[0] / r1[0];
}

// Kernel 5: mean over heads -> vals_mean
__global__ void mean_kernel(float* __restrict__ out)
{
    int t = threadIdx.x;  // 512
    out[t] = 0.25f * (g_val[t] + g_val[N_TOK + t] + g_val[2 * N_TOK + t] + g_val[3 * N_TOK + t]);
}

// =====================================================================
// Kernel 6: q_new / k_new = layernorm(x + mish(flat(px) @ Wxo^T + bxo))
//   flat[n, d*H + h] = pq[n, h*128 + d]
// grid (32, 2), 256 threads, dyn smem
// =====================================================================
__global__ void __launch_bounds__(256) qknew_kernel(
    const float* __restrict__ qin, const float* __restrict__ kin,
    const float* __restrict__ Wqo, const float* __restrict__ bqo,
    const float* __restrict__ Wko, const float* __restrict__ bko,
    const float* __restrict__ qg,  const float* __restrict__ qb,
    const float* __restrict__ kg,  const float* __restrict__ kb,
    float* __restrict__ out)
{
    extern __shared__ float sm[];
    float* s_flat = sm;                    // [16][512] raw proj rows
    float* Wsm    = sm + 16 * 512;         // [64][129]
    float* zs     = Wsm + 64 * 129;        // [16][64]
    float* mn     = zs + 16 * 64;          // [16]
    float* rs     = mn + 16;               // [16]

    const float* proj; const float* W; const float* bo; const float* xin;
    const float* g; const float* bt; float* o;
    if (blockIdx.y == 0) { proj = g_pq; W = Wqo; bo = bqo; xin = qin; g = qg; bt = qb; o = out; }
    else                 { proj = g_pk; W = Wko; bo = bko; xin = kin; g = kg; bt = kb; o = out + N_TOK * QDIM; }

    int n0 = blockIdx.x * 16;
    int t  = threadIdx.x;
    int oi = t & 63;
    int rseg = t >> 6;  // 0..3, rows rseg*4 .. rseg*4+3

    #pragma unroll
    for (int i = t; i < 16 * 128; i += 256)
        ((float4*)s_flat)[i] = ((const float4*)proj)[n0 * 128 + i];
    __syncthreads();

    float acc[4] = {0.f, 0.f, 0.f, 0.f};
    for (int jc = 0; jc < 4; jc++) {
        __syncthreads();
        #pragma unroll
        for (int i = t; i < 64 * 32; i += 256) {
            int oo = i >> 5, c4 = i & 31;
            float4 w = ((const float4*)W)[oo * 128 + jc * 32 + c4];
            float* dst = Wsm + oo * 129 + c4 * 4;
            dst[0] = w.x; dst[1] = w.y; dst[2] = w.z; dst[3] = w.w;
        }
        __syncthreads();
        #pragma unroll 4
        for (int jj = 0; jj < 128; jj++) {
            int j = jc * 128 + jj;
            int pidx = (j & 3) * 128 + (j >> 2);   // remap (d,h)-major flatten
            float w = Wsm[oi * 129 + jj];
            #pragma unroll
            for (int i = 0; i < 4; i++)
                acc[i] += s_flat[(rseg * 4 + i) * 512 + pidx] * w;
        }
    }

    #pragma unroll
    for (int i = 0; i < 4; i++) {
        int r = rseg * 4 + i;
        float x = acc[i] + bo[oi];
        zs[r * 64 + oi] = xin[(n0 + r) * QDIM + oi] + mishf(x);
    }
    __syncthreads();
    if (t < 16) {
        float s = 0.f;
        for (int c = 0; c < 64; c++) s += zs[t * 64 + c];
        float mean = s * (1.f / 64.f);
        float v2 = 0.f;
        for (int c = 0; c < 64; c++) { float d = zs[t * 64 + c] - mean; v2 += d * d; }
        mn[t] = mean;
        rs[t] = rsqrtf(v2 * (1.f / 64.f) + 1e-5f);
    }
    __syncthreads();
    #pragma unroll
    for (int i = 0; i < 4; i++) {
        int r = rseg * 4 + i;
        float zz = zs[r * 64 + oi];
        o[(n0 + r) * QDIM + oi] = (zz - mn[r]) * rs[r] * g[oi] + bt[oi];
    }
}

// =====================================================================
// launch
// =====================================================================
extern "C" void kernel_launch(void* const* d_in, const int* in_sizes, int n_in,
                              void* d_out, int out_size)
{
    const float* q    = (const float*)d_in[0];
    const float* k    = (const float*)d_in[1];
    const float* v    = (const float*)d_in[2];
    const float* bias = (const float*)d_in[3];
    const float* Wq   = (const float*)d_in[4];
    const float* bq   = (const float*)d_in[5];
    const float* Wk   = (const float*)d_in[6];
    const float* bk   = (const float*)d_in[7];
    const float* Wqo  = (const float*)d_in[8];
    const float* bqo  = (const float*)d_in[9];
    const float* Wko  = (const float*)d_in[10];
    const float* bko  = (const float*)d_in[11];
    const float* qg   = (const float*)d_in[12];
    const float* qb   = (const float*)d_in[13];
    const float* kg   = (const float*)d_in[14];
    const float* kb   = (const float*)d_in[15];
    const float* Wb   = (const float*)d_in[16];
    const float* bb   = (const float*)d_in[17];
    const float* Wbo  = (const float*)d_in[18];
    const float* bbo  = (const float*)d_in[19];

    float* out       = (float*)d_out;
    float* out_vals  = out + 2 * N_TOK * QDIM;             // 65536
    float* out_bias  = out_vals + N_TOK;                   // 66048

    const int SMEM1 = (ROWS * BD + ROWS * PS_PITCH + WS_FLOATS) * 4;   // 115712
    const int SMEM2 = (16 * 512 + 64 * 129 + 16 * 64 + 32) * 4;        // 70016
    cudaFuncSetAttribute(bias_fused_kernel, cudaFuncAttributeMaxDynamicSharedMemorySize, SMEM1);
    cudaFuncSetAttribute(qknew_kernel,      cudaFuncAttributeMaxDynamicSharedMemorySize, SMEM2);

    // projections (needed by logits + qknew)
    proj_kernel<<<dim3(N_TOK, 2), 256>>>(q, Wq, bq, k, Wk, bk);

    // big fused bias pipeline (bias_out + diffs)
    bias_fused_kernel<<<NN / ROWS, 256, SMEM1>>>(bias, Wb, bb, Wbo, bbo, out_bias);

    // logits = qk/sqrt(D) + diffs
    logits_kernel<<<dim3(N_TOK / 16, H_HEADS), 256>>>();

    // softmax + v
    softmax_v_kernel<<<H_HEADS * N_TOK, 256>>>(v);
    mean_kernel<<<1, N_TOK>>>(out_vals);

    // q_new / k_new heads
    qknew_kernel<<<dim3(N_TOK / 16, 2), 256, SMEM2>>>(
        q, k, Wqo, bqo, Wko, bko, qg, qb, kg, kb, out);
}

// round 4
// speedup vs baseline: 2.4488x; 2.4488x over previous
#include <cuda_runtime.h>
#include <cuda_bf16.h>
#include <math.h>
#include <stdint.h>

// ---- problem constants ----
#define N_TOK   512
#define QDIM    64
#define H_HEADS 4
#define D_HEAD  128
#define HD      512
#define BD      128
#define HBD     512
#define NN      (N_TOK * N_TOK)
#define INV_SQRT_D 0.08838834764831845f

// ---- scratch globals ----
__device__ float g_pq[N_TOK * HD];
__device__ float g_pk[N_TOK * HD];
__device__ float g_diffs[H_HEADS * NN];
__device__ float g_logits[H_HEADS * NN];
__device__ float g_val[H_HEADS * N_TOK];
// pre-split weights (bf16 hi/lo). Wbo reordered chunk-major: [nc][o][jj]
__device__ __nv_bfloat16 g_Wb_hi[HBD * BD];
__device__ __nv_bfloat16 g_Wb_lo[HBD * BD];
__device__ __nv_bfloat16 g_Wbo_hi[H_HEADS * BD * BD];
__device__ __nv_bfloat16 g_Wbo_lo[H_HEADS * BD * BD];

__device__ __forceinline__ float mishf(float x) {
    float sp = (x > 20.f) ? x : log1pf(expf(x));
    return x * tanhf(sp);
}
static __device__ __forceinline__ uint32_t pk2(__nv_bfloat16 a, __nv_bfloat16 b) {
    return (uint32_t)__bfloat16_as_ushort(a) | ((uint32_t)__bfloat16_as_ushort(b) << 16);
}

// warp-level bf16 MMA (sm_80+ PTX; works on bare sm_103 target)
static __device__ __forceinline__ void mma16816(float* d, const uint32_t* a,
                                                uint32_t b0, uint32_t b1) {
    asm volatile(
        "mma.sync.aligned.m16n8k16.row.col.f32.bf16.bf16.f32 "
        "{%0,%1,%2,%3}, {%4,%5,%6,%7}, {%8,%9}, {%0,%1,%2,%3};"
        : "+f"(d[0]), "+f"(d[1]), "+f"(d[2]), "+f"(d[3])
        : "r"(a[0]), "r"(a[1]), "r"(a[2]), "r"(a[3]), "r"(b0), "r"(b1));
}

// smem layout (bytes)
#define SMA_HI 0
#define SMA_LO 32768
#define SMW_HI 65536
#define SMW_LO 98304
#define SM_BB  131072
#define SM_BBO 133120
#define SM_TOT 133664

// =====================================================================
// Kernel 0: pre-split Wb / Wbo into bf16 hi/lo (Wbo chunk-major reorder)
// =====================================================================
__global__ void __launch_bounds__(256) prep_split(const float* __restrict__ Wb,
                                                  const float* __restrict__ Wbo)
{
    int i = blockIdx.x * 256 + threadIdx.x;
    if (i < HBD * BD) {
        float w = Wb[i];
        __nv_bfloat16 h = __float2bfloat16(w);
        g_Wb_hi[i] = h;
        g_Wb_lo[i] = __float2bfloat16(w - __bfloat162float(h));

        int o = i >> 9, j = i & 511;          // Wbo[o][j]
        int nc = j >> 7, jj = j & 127;
        float w2 = Wbo[i];
        __nv_bfloat16 h2 = __float2bfloat16(w2);
        int dst = nc * (BD * BD) + o * BD + jj;
        g_Wbo_hi[dst] = h2;
        g_Wbo_lo[dst] = __float2bfloat16(w2 - __bfloat162float(h2));
    }
}

// =====================================================================
// Kernel 1: q/k projections
// =====================================================================
__global__ void __launch_bounds__(256) proj_kernel(
    const float* __restrict__ q,  const float* __restrict__ Wq, const float* __restrict__ bq,
    const float* __restrict__ k,  const float* __restrict__ Wk, const float* __restrict__ bk)
{
    const float* x; const float* W; const float* b; float* out;
    if (blockIdx.y == 0) { x = q; W = Wq; b = bq; out = g_pq; }
    else                 { x = k; W = Wk; b = bk; out = g_pk; }
    int n = blockIdx.x;
    int t = threadIdx.x;
    __shared__ float xs[QDIM];
    if (t < QDIM/4) ((float4*)xs)[t] = ((const float4*)(x + n * QDIM))[t];
    __syncthreads();
    for (int j = t; j < HD; j += 256) {
        float s = b[j];
        const float4* wr = (const float4*)(W + j * QDIM);
        #pragma unroll
        for (int c = 0; c < QDIM/4; c++) {
            float4 w = wr[c];
            s += xs[4*c+0]*w.x + xs[4*c+1]*w.y + xs[4*c+2]*w.z + xs[4*c+3]*w.w;
        }
        out[n * HD + j] = s;
    }
}

// =====================================================================
// Kernel 2: fused bias pipeline on warp MMA (BF16x3 split)
// CTA = 128 pair-rows, 8 warps (warp w owns rows 16w..16w+15).
// Fragment-order SMEM staging:
//   A buf:  [mtile 8][ks 8][reg 4][lane 32] uint32 (hi & lo)
//   W buf:  [ntile 16][ks 8][reg 2][lane 32] uint32 (hi & lo)
// =====================================================================
__global__ void __launch_bounds__(256, 1) bias_fused_mma(
    const float* __restrict__ bias, const float* __restrict__ bb,
    const float* __restrict__ bbo,  float* __restrict__ bias_out)
{
    extern __shared__ char smc[];
    uint32_t* Ahi = (uint32_t*)(smc + SMA_HI);
    uint32_t* Alo = (uint32_t*)(smc + SMA_LO);
    uint32_t* Whi = (uint32_t*)(smc + SMW_HI);
    uint32_t* Wlo = (uint32_t*)(smc + SMW_LO);
    float*    bb_s  = (float*)(smc + SM_BB);
    float*    bbo_s = (float*)(smc + SM_BBO);

    int t = threadIdx.x, wid = t >> 5, lane = t & 31;
    int gq = lane >> 2, tt = lane & 3;
    int m0 = blockIdx.x * 128;

    if (t < 128) bbo_s[t] = bbo[t];
    bb_s[t] = bb[t]; bb_s[t + 256] = bb[t + 256];

    // ---- stage bias tile -> A frag buffers (hi/lo) ----
    {
        const float4* src = (const float4*)(bias + (size_t)m0 * BD);
        #pragma unroll
        for (int i = t; i < 4096; i += 256) {
            int r = i >> 5, c = (i & 31) << 2;
            float4 v = src[i];
            __nv_bfloat16 h0 = __float2bfloat16(v.x), h1 = __float2bfloat16(v.y);
            __nv_bfloat16 h2 = __float2bfloat16(v.z), h3 = __float2bfloat16(v.w);
            __nv_bfloat16 l0 = __float2bfloat16(v.x - __bfloat162float(h0));
            __nv_bfloat16 l1 = __float2bfloat16(v.y - __bfloat162float(h1));
            __nv_bfloat16 l2 = __float2bfloat16(v.z - __bfloat162float(h2));
            __nv_bfloat16 l3 = __float2bfloat16(v.w - __bfloat162float(h3));
            int mt = r >> 4, g = r & 15, ks = c >> 4, cl = c & 15;
            int reg = ((cl >= 8) ? 2 : 0) + ((g >= 8) ? 1 : 0);
            int ln0 = (g & 7) * 4 + ((cl & 7) >> 1);
            int idx = ((mt * 8 + ks) * 4 + reg) * 32 + ln0;
            *(uint2*)(Ahi + idx) = make_uint2(pk2(h0, h1), pk2(h2, h3));
            *(uint2*)(Alo + idx) = make_uint2(pk2(l0, l1), pk2(l2, l3));
        }
    }

    float O[16][4];
    #pragma unroll
    for (int j = 0; j < 16; j++)
        #pragma unroll
        for (int r = 0; r < 4; r++) O[j][r] = 0.f;

    for (int nc = 0; nc < 4; nc++) {
        __syncthreads();   // previous readers of W buffer done (or A staging, chunk 0)
        // ---- stage Wb chunk into W frag buffers ----
        {
            const uint4* sh = (const uint4*)(g_Wb_hi + nc * (BD * BD));
            const uint4* sl = (const uint4*)(g_Wb_lo + nc * (BD * BD));
            #pragma unroll
            for (int i = t; i < 2048; i += 256) {
                int n = i >> 4, k8 = i & 15;
                int nt = n >> 3, g = n & 7, ks = k8 >> 1, reg = k8 & 1;
                int idx = (((nt * 8 + ks) * 2 + reg) * 32 + g * 4);
                *(uint4*)(Whi + idx) = sh[i];
                *(uint4*)(Wlo + idx) = sl[i];
            }
        }
        __syncthreads();

        // ---- GEMM1: D1 = A @ Wb^T (3-pass bf16) ----
        float D1[16][4];
        #pragma unroll
        for (int j = 0; j < 16; j++)
            #pragma unroll
            for (int r = 0; r < 4; r++) D1[j][r] = 0.f;

        #pragma unroll
        for (int ks = 0; ks < 8; ks++) {
            uint32_t ah[4], al[4];
            int ab = (wid * 8 + ks) * 128;
            #pragma unroll
            for (int r = 0; r < 4; r++) {
                ah[r] = Ahi[ab + r * 32 + lane];
                al[r] = Alo[ab + r * 32 + lane];
            }
            #pragma unroll
            for (int j = 0; j < 16; j++) {
                int wb = ((j * 8 + ks) * 2) * 32 + lane;
                uint32_t b0h = Whi[wb], b1h = Whi[wb + 32];
                uint32_t b0l = Wlo[wb], b1l = Wlo[wb + 32];
                mma16816(D1[j], ah, b0h, b1h);
                mma16816(D1[j], ah, b0l, b1l);
                mma16816(D1[j], al, b0h, b1h);
            }
        }

        // ---- convert: P = D1 + bb -> bf16 hi/lo frags (registers) + norms ----
        uint32_t Phi[32], Plo[32];
        float sqlo = 0.f, sqhi = 0.f;
        #pragma unroll
        for (int j = 0; j < 16; j++) {
            float b0 = bb_s[nc * 128 + j * 8 + 2 * tt];
            float b1 = bb_s[nc * 128 + j * 8 + 2 * tt + 1];
            float p0 = D1[j][0] + b0, p1 = D1[j][1] + b1;
            float p2 = D1[j][2] + b0, p3 = D1[j][3] + b1;
            sqlo += p0 * p0 + p1 * p1;
            sqhi += p2 * p2 + p3 * p3;
            __nv_bfloat16 h0 = __float2bfloat16(p0), h1 = __float2bfloat16(p1);
            __nv_bfloat16 h2 = __float2bfloat16(p2), h3 = __float2bfloat16(p3);
            Phi[2*j]   = pk2(h0, h1);
            Phi[2*j+1] = pk2(h2, h3);
            Plo[2*j]   = pk2(__float2bfloat16(p0 - __bfloat162float(h0)),
                             __float2bfloat16(p1 - __bfloat162float(h1)));
            Plo[2*j+1] = pk2(__float2bfloat16(p2 - __bfloat162float(h2)),
                             __float2bfloat16(p3 - __bfloat162float(h3)));
        }
        sqlo += __shfl_xor_sync(0xFFFFFFFF, sqlo, 1);
        sqlo += __shfl_xor_sync(0xFFFFFFFF, sqlo, 2);
        sqhi += __shfl_xor_sync(0xFFFFFFFF, sqhi, 1);
        sqhi += __shfl_xor_sync(0xFFFFFFFF, sqhi, 2);
        if (tt == 0) {
            int row = m0 + wid * 16 + gq;
            g_diffs[(size_t)nc * NN + row]     = sqrtf(sqlo);
            g_diffs[(size_t)nc * NN + row + 8] = sqrtf(sqhi);
        }

        __syncthreads();   // all warps done reading Wb buffer
        // ---- stage Wbo chunk ----
        {
            const uint4* sh = (const uint4*)(g_Wbo_hi + nc * (BD * BD));
            const uint4* sl = (const uint4*)(g_Wbo_lo + nc * (BD * BD));
            #pragma unroll
            for (int i = t; i < 2048; i += 256) {
                int n = i >> 4, k8 = i & 15;
                int nt = n >> 3, g = n & 7, ks = k8 >> 1, reg = k8 & 1;
                int idx = (((nt * 8 + ks) * 2 + reg) * 32 + g * 4);
                *(uint4*)(Whi + idx) = sh[i];
                *(uint4*)(Wlo + idx) = sl[i];
            }
        }
        __syncthreads();

        // ---- GEMM2: O += P @ Wbo^T (3-pass bf16, A operand in registers) ----
        #pragma unroll
        for (int ks = 0; ks < 8; ks++) {
            const uint32_t* ph = &Phi[4 * ks];
            const uint32_t* pl = &Plo[4 * ks];
            #pragma unroll
            for (int j = 0; j < 16; j++) {
                int wb = ((j * 8 + ks) * 2) * 32 + lane;
                uint32_t b0h = Whi[wb], b1h = Whi[wb + 32];
                uint32_t b0l = Wlo[wb], b1l = Wlo[wb + 32];
                mma16816(O[j], ph, b0h, b1h);
                mma16816(O[j], ph, b0l, b1l);
                mma16816(O[j], pl, b0h, b1h);
            }
        }
    }

    // ---- final: O + bbo, mish -> gmem (32B-sector aligned float2 stores) ----
    int row = m0 + wid * 16 + gq;
    #pragma unroll
    for (int j = 0; j < 16; j++) {
        int col = j * 8 + 2 * tt;
        float b0 = bbo_s[col], b1 = bbo_s[col + 1];
        float2 v0, v1;
        v0.x = mishf(O[j][0] + b0);  v0.y = mishf(O[j][1] + b1);
        v1.x = mishf(O[j][2] + b0);  v1.y = mishf(O[j][3] + b1);
        *(float2*)(bias_out + (size_t)row * BD + col)       = v0;
        *(float2*)(bias_out + (size_t)(row + 8) * BD + col) = v1;
    }
}

// =====================================================================
// Kernel 3: logits
// =====================================================================
__global__ void __launch_bounds__(256) logits_kernel()
{
    __shared__ float pq_s[16 * 128];
    __shared__ float pk_s[64 * 129];
    int q0 = blockIdx.x * 16;
    int h  = blockIdx.y;
    int t  = threadIdx.x;
    int qi = t >> 4;
    int kx = t & 15;

    #pragma unroll
    for (int i = t; i < 16 * 32; i += 256) {
        int r = i >> 5, c4 = i & 31;
        ((float4*)pq_s)[r * 32 + c4] = ((const float4*)g_pq)[(q0 + r) * 128 + h * 32 + c4];
    }

    for (int kc = 0; kc < 8; kc++) {
        __syncthreads();
        #pragma unroll
        for (int i = t; i < 64 * 32; i += 256) {
            int r = i >> 5, c4 = i & 31;
            float4 w = ((const float4*)g_pk)[(kc * 64 + r) * 128 + h * 32 + c4];
            float* dst = pk_s + r * 129 + c4 * 4;
            dst[0] = w.x; dst[1] = w.y; dst[2] = w.z; dst[3] = w.w;
        }
        __syncthreads();

        float acc0 = 0, acc1 = 0, acc2 = 0, acc3 = 0;
        const float* ap = pq_s + qi * 128;
        const float* k0 = pk_s + (kx * 4    ) * 129;
        const float* k1 = pk_s + (kx * 4 + 1) * 129;
        const float* k2 = pk_s + (kx * 4 + 2) * 129;
        const float* k3 = pk_s + (kx * 4 + 3) * 129;
        #pragma unroll 8
        for (int d = 0; d < 128; d++) {
            float a = ap[d];
            acc0 += a * k0[d]; acc1 += a * k1[d];
            acc2 += a * k2[d]; acc3 += a * k3[d];
        }
        size_t base = (size_t)h * NN + (size_t)(q0 + qi) * N_TOK + kc * 64 + kx * 4;
        float4 dsum = *(const float4*)(g_diffs + base);
        float4 o;
        o.x = acc0 * INV_SQRT_D + dsum.x;
        o.y = acc1 * INV_SQRT_D + dsum.y;
        o.z = acc2 * INV_SQRT_D + dsum.z;
        o.w = acc3 * INV_SQRT_D + dsum.w;
        *(float4*)(g_logits + base) = o;
    }
}

// =====================================================================
// Kernel 4: softmax + v
// =====================================================================
__global__ void __launch_bounds__(256) softmax_v_kernel(const float* __restrict__ v)
{
    __shared__ float r1[256];
    __shared__ float r2[256];
    int hq = blockIdx.x;
    int t  = threadIdx.x;
    const float* lr = g_logits + (size_t)hq * N_TOK;
    float l0 = lr[t], l1 = lr[t + 256];
    float m = fmaxf(l0, l1);
    r1[t] = m;
    __syncthreads();
    #pragma unroll
    for (int s = 128; s > 0; s >>= 1) {
        if (t < s) r1[t] = fmaxf(r1[t], r1[t + s]);
        __syncthreads();
    }
    m = r1[0];
    __syncthreads();
    float e0 = expf(l0 - m), e1 = expf(l1 - m);
    r1[t] = e0 + e1;
    r2[t] = e0 * v[t] + e1 * v[t + 256];
    __syncthreads();
    #pragma unroll
    for (int s = 128; s > 0; s >>= 1) {
        if (t < s) { r1[t] += r1[t + s]; r2[t] += r2[t + s]; }
        __syncthreads();
    }
    if (t == 0) g_val[hq] = r2[0] / r1[0];
}

__global__ void mean_kernel(float* __restrict__ out)
{
    int t = threadIdx.x;
    out[t] = 0.25f * (g_val[t] + g_val[N_TOK + t] + g_val[2 * N_TOK + t] + g_val[3 * N_TOK + t]);
}

// =====================================================================
// Kernel 6: q_new / k_new heads
// =====================================================================
__global__ void __launch_bounds__(256) qknew_kernel(
    const float* __restrict__ qin, const float* __restrict__ kin,
    const float* __restrict__ Wqo, const float* __restrict__ bqo,
    const float* __restrict__ Wko, const float* __restrict__ bko,
    const float* __restrict__ qg,  const float* __restrict__ qb,
    const float* __restrict__ kg,  const float* __restrict__ kb,
    float* __restrict__ out)
{
    extern __shared__ float sm[];
    float* s_flat = sm;
    float* Wsm    = sm + 16 * 512;
    float* zs     = Wsm + 64 * 129;
    float* mn     = zs + 16 * 64;
    float* rs     = mn + 16;

    const float* proj; const float* W; const float* bo; const float* xin;
    const float* g; const float* bt; float* o;
    if (blockIdx.y == 0) { proj = g_pq; W = Wqo; bo = bqo; xin = qin; g = qg; bt = qb; o = out; }
    else                 { proj = g_pk; W = Wko; bo = bko; xin = kin; g = kg; bt = kb; o = out + N_TOK * QDIM; }

    int n0 = blockIdx.x * 16;
    int t  = threadIdx.x;
    int oi = t & 63;
    int rseg = t >> 6;

    #pragma unroll
    for (int i = t; i < 16 * 128; i += 256)
        ((float4*)s_flat)[i] = ((const float4*)proj)[n0 * 128 + i];
    __syncthreads();

    float acc[4] = {0.f, 0.f, 0.f, 0.f};
    for (int jc = 0; jc < 4; jc++) {
        __syncthreads();
        #pragma unroll
        for (int i = t; i < 64 * 32; i += 256) {
            int oo = i >> 5, c4 = i & 31;
            float4 w = ((const float4*)W)[oo * 128 + jc * 32 + c4];
            float* dst = Wsm + oo * 129 + c4 * 4;
            dst[0] = w.x; dst[1] = w.y; dst[2] = w.z; dst[3] = w.w;
        }
        __syncthreads();
        #pragma unroll 4
        for (int jj = 0; jj < 128; jj++) {
            int j = jc * 128 + jj;
            int pidx = (j & 3) * 128 + (j >> 2);
            float w = Wsm[oi * 129 + jj];
            #pragma unroll
            for (int i = 0; i < 4; i++)
                acc[i] += s_flat[(rseg * 4 + i) * 512 + pidx] * w;
        }
    }

    #pragma unroll
    for (int i = 0; i < 4; i++) {
        int r = rseg * 4 + i;
        float x = acc[i] + bo[oi];
        zs[r * 64 + oi] = xin[(n0 + r) * QDIM + oi] + mishf(x);
    }
    __syncthreads();
    if (t < 16) {
        float s = 0.f;
        for (int c = 0; c < 64; c++) s += zs[t * 64 + c];
        float mean = s * (1.f / 64.f);
        float v2 = 0.f;
        for (int c = 0; c < 64; c++) { float d = zs[t * 64 + c] - mean; v2 += d * d; }
        mn[t] = mean;
        rs[t] = rsqrtf(v2 * (1.f / 64.f) + 1e-5f);
    }
    __syncthreads();
    #pragma unroll
    for (int i = 0; i < 4; i++) {
        int r = rseg * 4 + i;
        float zz = zs[r * 64 + oi];
        o[(n0 + r) * QDIM + oi] = (zz - mn[r]) * rs[r] * g[oi] + bt[oi];
    }
}

// =====================================================================
// launch
// =====================================================================
extern "C" void kernel_launch(void* const* d_in, const int* in_sizes, int n_in,
                              void* d_out, int out_size)
{
    const float* q    = (const float*)d_in[0];
    const float* k    = (const float*)d_in[1];
    const float* v    = (const float*)d_in[2];
    const float* bias = (const float*)d_in[3];
    const float* Wq   = (const float*)d_in[4];
    const float* bq   = (const float*)d_in[5];
    const float* Wk   = (const float*)d_in[6];
    const float* bk   = (const float*)d_in[7];
    const float* Wqo  = (const float*)d_in[8];
    const float* bqo  = (const float*)d_in[9];
    const float* Wko  = (const float*)d_in[10];
    const float* bko  = (const float*)d_in[11];
    const float* qg   = (const float*)d_in[12];
    const float* qb   = (const float*)d_in[13];
    const float* kg   = (const float*)d_in[14];
    const float* kb   = (const float*)d_in[15];
    const float* Wb   = (const float*)d_in[16];
    const float* bb   = (const float*)d_in[17];
    const float* Wbo  = (const float*)d_in[18];
    const float* bbo  = (const float*)d_in[19];

    float* out       = (float*)d_out;
    float* out_vals  = out + 2 * N_TOK * QDIM;
    float* out_bias  = out_vals + N_TOK;

    const int SMEM2 = (16 * 512 + 64 * 129 + 16 * 64 + 32) * 4;
    cudaFuncSetAttribute(bias_fused_mma, cudaFuncAttributeMaxDynamicSharedMemorySize, SM_TOT);
    cudaFuncSetAttribute(qknew_kernel,   cudaFuncAttributeMaxDynamicSharedMemorySize, SMEM2);

    prep_split<<<(HBD * BD + 255) / 256, 256>>>(Wb, Wbo);
    proj_kernel<<<dim3(N_TOK, 2), 256>>>(q, Wq, bq, k, Wk, bk);

    bias_fused_mma<<<NN / 128, 256, SM_TOT>>>(bias, bb, bbo, out_bias);

    logits_kernel<<<dim3(N_TOK / 16, H_HEADS), 256>>>();
    softmax_v_kernel<<<H_HEADS * N_TOK, 256>>>(v);
    mean_kernel<<<1, N_TOK>>>(out_vals);
    qknew_kernel<<<dim3(N_TOK / 16, 2), 256, SMEM2>>>(
        q, k, Wqo, bqo, Wko, bko, qg, qb, kg, kb, out);
}

// round 5
// speedup vs baseline: 2.4995x; 1.0207x over previous
#include <cuda_runtime.h>
#include <cuda_bf16.h>
#include <math.h>
#include <stdint.h>

// ---- problem constants ----
#define N_TOK   512
#define QDIM    64
#define H_HEADS 4
#define D_HEAD  128
#define HD      512
#define BD      128
#define HBD     512
#define NN      (N_TOK * N_TOK)
#define INV_SQRT_D 0.08838834764831845f

// ---- scratch globals ----
__device__ float g_pq[N_TOK * HD];
__device__ float g_pk[N_TOK * HD];
__device__ float g_diffs[H_HEADS * NN];
__device__ float g_logits[H_HEADS * NN];
__device__ float g_val[H_HEADS * N_TOK];
// pre-split weights (bf16 hi/lo). Wbo reordered chunk-major: [nc][o][jj]
__device__ __nv_bfloat16 g_Wb_hi[HBD * BD];
__device__ __nv_bfloat16 g_Wb_lo[HBD * BD];
__device__ __nv_bfloat16 g_Wbo_hi[H_HEADS * BD * BD];
__device__ __nv_bfloat16 g_Wbo_lo[H_HEADS * BD * BD];

__device__ __forceinline__ float mishf(float x) {
    float sp = (x > 20.f) ? x : log1pf(expf(x));
    return x * tanhf(sp);
}
static __device__ __forceinline__ uint32_t pk2(__nv_bfloat16 a, __nv_bfloat16 b) {
    return (uint32_t)__bfloat16_as_ushort(a) | ((uint32_t)__bfloat16_as_ushort(b) << 16);
}

// warp-level bf16 MMA (sm_80+ PTX; works on bare sm_103 target)
static __device__ __forceinline__ void mma16816(float* d, const uint32_t* a,
                                                uint32_t b0, uint32_t b1) {
    asm volatile(
        "mma.sync.aligned.m16n8k16.row.col.f32.bf16.bf16.f32 "
        "{%0,%1,%2,%3}, {%4,%5,%6,%7}, {%8,%9}, {%0,%1,%2,%3};"
        : "+f"(d[0]), "+f"(d[1]), "+f"(d[2]), "+f"(d[3])
        : "r"(a[0]), "r"(a[1]), "r"(a[2]), "r"(a[3]), "r"(b0), "r"(b1));
}

// smem layout (bytes)
#define SMA_HI  0
#define SMA_LO  32768
#define SMW_HI  65536
#define SMW_LO  98304
#define SMP_HI  131072
#define SMP_LO  163840
#define SM_BB   196608
#define SM_BBO  198656
#define SM_PART 199168
#define SM_TOT  200192

// =====================================================================
// Kernel 0: pre-split Wb / Wbo into bf16 hi/lo (Wbo chunk-major reorder)
// =====================================================================
__global__ void __launch_bounds__(256) prep_split(const float* __restrict__ Wb,
                                                  const float* __restrict__ Wbo)
{
    int i = blockIdx.x * 256 + threadIdx.x;
    if (i < HBD * BD) {
        float w = Wb[i];
        __nv_bfloat16 h = __float2bfloat16(w);
        g_Wb_hi[i] = h;
        g_Wb_lo[i] = __float2bfloat16(w - __bfloat162float(h));

        int o = i >> 9, j = i & 511;          // Wbo[o][j]
        int nc = j >> 7, jj = j & 127;
        float w2 = Wbo[i];
        __nv_bfloat16 h2 = __float2bfloat16(w2);
        int dst = nc * (BD * BD) + o * BD + jj;
        g_Wbo_hi[dst] = h2;
        g_Wbo_lo[dst] = __float2bfloat16(w2 - __bfloat162float(h2));
    }
}

// =====================================================================
// Kernel 1: q/k projections
// =====================================================================
__global__ void __launch_bounds__(256) proj_kernel(
    const float* __restrict__ q,  const float* __restrict__ Wq, const float* __restrict__ bq,
    const float* __restrict__ k,  const float* __restrict__ Wk, const float* __restrict__ bk)
{
    const float* x; const float* W; const float* b; float* out;
    if (blockIdx.y == 0) { x = q; W = Wq; b = bq; out = g_pq; }
    else                 { x = k; W = Wk; b = bk; out = g_pk; }
    int n = blockIdx.x;
    int t = threadIdx.x;
    __shared__ float xs[QDIM];
    if (t < QDIM/4) ((float4*)xs)[t] = ((const float4*)(x + n * QDIM))[t];
    __syncthreads();
    for (int j = t; j < HD; j += 256) {
        float s = b[j];
        const float4* wr = (const float4*)(W + j * QDIM);
        #pragma unroll
        for (int c = 0; c < QDIM/4; c++) {
            float4 w = wr[c];
            s += xs[4*c+0]*w.x + xs[4*c+1]*w.y + xs[4*c+2]*w.z + xs[4*c+3]*w.w;
        }
        out[n * HD + j] = s;
    }
}

// =====================================================================
// Kernel 2: fused bias pipeline on warp MMA (BF16x3 split)
// 512 threads, 16 warps. Warp (m = w&7, nhalf = w>>3):
//   rows 16m..16m+15, output cols nhalf*64..+63.
// P exchanged through SMEM in A-fragment layout (D-frag == A-frag bitwise).
// Frag layouts:
//   A/P buf: [mtile 8][ks 8][reg 4][lane 32] uint32 (hi & lo)
//   W buf:   [ntile 16][ks 8][reg 2][lane 32] uint32 (hi & lo)
// =====================================================================
__global__ void __launch_bounds__(512, 1) bias_fused_mma(
    const float* __restrict__ bias, const float* __restrict__ bb,
    const float* __restrict__ bbo,  float* __restrict__ bias_out)
{
    extern __shared__ char smc[];
    uint32_t* Ahi = (uint32_t*)(smc + SMA_HI);
    uint32_t* Alo = (uint32_t*)(smc + SMA_LO);
    uint32_t* Whi = (uint32_t*)(smc + SMW_HI);
    uint32_t* Wlo = (uint32_t*)(smc + SMW_LO);
    uint32_t* Phi = (uint32_t*)(smc + SMP_HI);
    uint32_t* Plo = (uint32_t*)(smc + SMP_LO);
    float*    bb_s  = (float*)(smc + SM_BB);
    float*    bbo_s = (float*)(smc + SM_BBO);
    float*    part  = (float*)(smc + SM_PART);

    int t = threadIdx.x, wid = t >> 5, lane = t & 31;
    int gq = lane >> 2, tt = lane & 3;
    int m  = wid & 7;         // row-tile (16 rows)
    int nh = wid >> 3;        // column half (0: cols 0-63, 1: cols 64-127)
    int m0 = blockIdx.x * 128;

    if (t < 128) bbo_s[t] = bbo[t];
    if (t < 512) bb_s[t] = bb[t];

    // ---- stage bias tile -> A frag buffers (hi/lo) ----
    {
        const float4* src = (const float4*)(bias + (size_t)m0 * BD);
        #pragma unroll
        for (int i = t; i < 4096; i += 512) {
            int r = i >> 5, c = (i & 31) << 2;
            float4 v = src[i];
            __nv_bfloat16 h0 = __float2bfloat16(v.x), h1 = __float2bfloat16(v.y);
            __nv_bfloat16 h2 = __float2bfloat16(v.z), h3 = __float2bfloat16(v.w);
            __nv_bfloat16 l0 = __float2bfloat16(v.x - __bfloat162float(h0));
            __nv_bfloat16 l1 = __float2bfloat16(v.y - __bfloat162float(h1));
            __nv_bfloat16 l2 = __float2bfloat16(v.z - __bfloat162float(h2));
            __nv_bfloat16 l3 = __float2bfloat16(v.w - __bfloat162float(h3));
            int mt = r >> 4, g = r & 15, ks = c >> 4, cl = c & 15;
            int reg = ((cl >= 8) ? 2 : 0) + ((g >= 8) ? 1 : 0);
            int ln0 = (g & 7) * 4 + ((cl & 7) >> 1);
            int idx = ((mt * 8 + ks) * 4 + reg) * 32 + ln0;
            *(uint2*)(Ahi + idx) = make_uint2(pk2(h0, h1), pk2(h2, h3));
            *(uint2*)(Alo + idx) = make_uint2(pk2(l0, l1), pk2(l2, l3));
        }
    }

    float O[8][4];
    #pragma unroll
    for (int j = 0; j < 8; j++)
        #pragma unroll
        for (int r = 0; r < 4; r++) O[j][r] = 0.f;

    for (int nc = 0; nc < 4; nc++) {
        __syncthreads();   // previous readers of W/P buffers done
        // ---- stage Wb chunk ----
        {
            const uint4* sh = (const uint4*)(g_Wb_hi + nc * (BD * BD));
            const uint4* sl = (const uint4*)(g_Wb_lo + nc * (BD * BD));
            #pragma unroll
            for (int i = t; i < 2048; i += 512) {
                int n = i >> 4, k8 = i & 15;
                int nt = n >> 3, g = n & 7, ks = k8 >> 1, reg = k8 & 1;
                int idx = (((nt * 8 + ks) * 2 + reg) * 32 + g * 4);
                *(uint4*)(Whi + idx) = sh[i];
                *(uint4*)(Wlo + idx) = sl[i];
            }
        }
        __syncthreads();

        // ---- GEMM1: D1 = A @ Wb^T (3-pass bf16), 64 output cols per warp ----
        float D1[8][4];
        #pragma unroll
        for (int j = 0; j < 8; j++)
            #pragma unroll
            for (int r = 0; r < 4; r++) D1[j][r] = 0.f;

        #pragma unroll
        for (int ks = 0; ks < 8; ks++) {
            uint32_t ah[4], al[4];
            int ab = (m * 8 + ks) * 128;
            #pragma unroll
            for (int r = 0; r < 4; r++) {
                ah[r] = Ahi[ab + r * 32 + lane];
                al[r] = Alo[ab + r * 32 + lane];
            }
            #pragma unroll
            for (int j = 0; j < 8; j++) {
                int jt = nh * 8 + j;
                int wb = ((jt * 8 + ks) * 2) * 32 + lane;
                uint32_t b0h = Whi[wb], b1h = Whi[wb + 32];
                uint32_t b0l = Wlo[wb], b1l = Wlo[wb + 32];
                mma16816(D1[j], ah, b0h, b1h);
                mma16816(D1[j], ah, b0l, b1l);
                mma16816(D1[j], al, b0h, b1h);
            }
        }

        // ---- convert: P = D1 + bb -> bf16 hi/lo -> SMEM P frags; norms ----
        float sqlo = 0.f, sqhi = 0.f;
        #pragma unroll
        for (int j = 0; j < 8; j++) {
            int jt = nh * 8 + j;
            float b0 = bb_s[nc * 128 + jt * 8 + 2 * tt];
            float b1 = bb_s[nc * 128 + jt * 8 + 2 * tt + 1];
            float p0 = D1[j][0] + b0, p1 = D1[j][1] + b1;
            float p2 = D1[j][2] + b0, p3 = D1[j][3] + b1;
            sqlo += p0 * p0 + p1 * p1;
            sqhi += p2 * p2 + p3 * p3;
            __nv_bfloat16 h0 = __float2bfloat16(p0), h1 = __float2bfloat16(p1);
            __nv_bfloat16 h2 = __float2bfloat16(p2), h3 = __float2bfloat16(p3);
            // D-frag == A-frag: rows g -> reg (hi8*2), rows g+8 -> reg (hi8*2+1)
            int s = jt >> 1, hi8 = jt & 1;
            int i0 = ((m * 8 + s) * 4 + hi8 * 2) * 32 + lane;
            Phi[i0]      = pk2(h0, h1);
            Phi[i0 + 32] = pk2(h2, h3);
            Plo[i0]      = pk2(__float2bfloat16(p0 - __bfloat162float(h0)),
                               __float2bfloat16(p1 - __bfloat162float(h1)));
            Plo[i0 + 32] = pk2(__float2bfloat16(p2 - __bfloat162float(h2)),
                               __float2bfloat16(p3 - __bfloat162float(h3)));
        }
        sqlo += __shfl_xor_sync(0xFFFFFFFF, sqlo, 1);
        sqlo += __shfl_xor_sync(0xFFFFFFFF, sqlo, 2);
        sqhi += __shfl_xor_sync(0xFFFFFFFF, sqhi, 1);
        sqhi += __shfl_xor_sync(0xFFFFFFFF, sqhi, 2);
        if (tt == 0) {
            part[nh * 128 + m * 16 + gq]     = sqlo;
            part[nh * 128 + m * 16 + gq + 8] = sqhi;
        }

        __syncthreads();   // P frags + norm partials complete; Wb reads done

        // ---- combine norms; stage Wbo chunk ----
        if (t < 128)
            g_diffs[(size_t)nc * NN + m0 + t] = sqrtf(part[t] + part[128 + t]);
        {
            const uint4* sh = (const uint4*)(g_Wbo_hi + nc * (BD * BD));
            const uint4* sl = (const uint4*)(g_Wbo_lo + nc * (BD * BD));
            #pragma unroll
            for (int i = t; i < 2048; i += 512) {
                int n = i >> 4, k8 = i & 15;
                int nt = n >> 3, g = n & 7, ks = k8 >> 1, reg = k8 & 1;
                int idx = (((nt * 8 + ks) * 2 + reg) * 32 + g * 4);
                *(uint4*)(Whi + idx) = sh[i];
                *(uint4*)(Wlo + idx) = sl[i];
            }
        }
        __syncthreads();

        // ---- GEMM2: O += P @ Wbo^T (3-pass bf16) ----
        #pragma unroll
        for (int ks = 0; ks < 8; ks++) {
            uint32_t ph[4], pl[4];
            int pb = (m * 8 + ks) * 128;
            #pragma unroll
            for (int r = 0; r < 4; r++) {
                ph[r] = Phi[pb + r * 32 + lane];
                pl[r] = Plo[pb + r * 32 + lane];
            }
            #pragma unroll
            for (int j = 0; j < 8; j++) {
                int jt = nh * 8 + j;
                int wb = ((jt * 8 + ks) * 2) * 32 + lane;
                uint32_t b0h = Whi[wb], b1h = Whi[wb + 32];
                uint32_t b0l = Wlo[wb], b1l = Wlo[wb + 32];
                mma16816(O[j], ph, b0h, b1h);
                mma16816(O[j], ph, b0l, b1l);
                mma16816(O[j], pl, b0h, b1h);
            }
        }
    }

    // ---- final: O + bbo, mish -> gmem ----
    int row = m0 + m * 16 + gq;
    #pragma unroll
    for (int j = 0; j < 8; j++) {
        int col = nh * 64 + j * 8 + 2 * tt;
        float b0 = bbo_s[col], b1 = bbo_s[col + 1];
        float2 v0, v1;
        v0.x = mishf(O[j][0] + b0);  v0.y = mishf(O[j][1] + b1);
        v1.x = mishf(O[j][2] + b0);  v1.y = mishf(O[j][3] + b1);
        *(float2*)(bias_out + (size_t)row * BD + col)       = v0;
        *(float2*)(bias_out + (size_t)(row + 8) * BD + col) = v1;
    }
}

// =====================================================================
// Kernel 3: logits  (parallel over k-chunks: grid (32, 4, 8))
// =====================================================================
__global__ void __launch_bounds__(256) logits_kernel()
{
    __shared__ float pq_s[16 * 128];
    __shared__ float pk_s[64 * 129];
    int q0 = blockIdx.x * 16;
    int h  = blockIdx.y;
    int kc = blockIdx.z;
    int t  = threadIdx.x;
    int qi = t >> 4;
    int kx = t & 15;

    #pragma unroll
    for (int i = t; i < 16 * 32; i += 256) {
        int r = i >> 5, c4 = i & 31;
        ((float4*)pq_s)[r * 32 + c4] = ((const float4*)g_pq)[(q0 + r) * 128 + h * 32 + c4];
    }
    #pragma unroll
    for (int i = t; i < 64 * 32; i += 256) {
        int r = i >> 5, c4 = i & 31;
        float4 w = ((const float4*)g_pk)[(kc * 64 + r) * 128 + h * 32 + c4];
        float* dst = pk_s + r * 129 + c4 * 4;
        dst[0] = w.x; dst[1] = w.y; dst[2] = w.z; dst[3] = w.w;
    }
    __syncthreads();

    float acc0 = 0, acc1 = 0, acc2 = 0, acc3 = 0;
    const float* ap = pq_s + qi * 128;
    const float* k0 = pk_s + (kx * 4    ) * 129;
    const float* k1 = pk_s + (kx * 4 + 1) * 129;
    const float* k2 = pk_s + (kx * 4 + 2) * 129;
    const float* k3 = pk_s + (kx * 4 + 3) * 129;
    #pragma unroll 8
    for (int d = 0; d < 128; d++) {
        float a = ap[d];
        acc0 += a * k0[d]; acc1 += a * k1[d];
        acc2 += a * k2[d]; acc3 += a * k3[d];
    }
    size_t base = (size_t)h * NN + (size_t)(q0 + qi) * N_TOK + kc * 64 + kx * 4;
    float4 dsum = *(const float4*)(g_diffs + base);
    float4 o;
    o.x = acc0 * INV_SQRT_D + dsum.x;
    o.y = acc1 * INV_SQRT_D + dsum.y;
    o.z = acc2 * INV_SQRT_D + dsum.z;
    o.w = acc3 * INV_SQRT_D + dsum.w;
    *(float4*)(g_logits + base) = o;
}

// =====================================================================
// Kernel 4: softmax + v
// =====================================================================
__global__ void __launch_bounds__(256) softmax_v_kernel(const float* __restrict__ v)
{
    __shared__ float r1[256];
    __shared__ float r2[256];
    int hq = blockIdx.x;
    int t  = threadIdx.x;
    const float* lr = g_logits + (size_t)hq * N_TOK;
    float l0 = lr[t], l1 = lr[t + 256];
    float m = fmaxf(l0, l1);
    r1[t] = m;
    __syncthreads();
    #pragma unroll
    for (int s = 128; s > 0; s >>= 1) {
        if (t < s) r1[t] = fmaxf(r1[t], r1[t + s]);
        __syncthreads();
    }
    m = r1[0];
    __syncthreads();
    float e0 = expf(l0 - m), e1 = expf(l1 - m);
    r1[t] = e0 + e1;
    r2[t] = e0 * v[t] + e1 * v[t + 256];
    __syncthreads();
    #pragma unroll
    for (int s = 128; s > 0; s >>= 1) {
        if (t < s) { r1[t] += r1[t + s]; r2[t] += r2[t + s]; }
        __syncthreads();
    }
    if (t == 0) g_val[hq] = r2[0] / r1[0];
}

__global__ void mean_kernel(float* __restrict__ out)
{
    int t = threadIdx.x;
    out[t] = 0.25f * (g_val[t] + g_val[N_TOK + t] + g_val[2 * N_TOK + t] + g_val[3 * N_TOK + t]);
}

// =====================================================================
// Kernel 6: q_new / k_new heads
// =====================================================================
__global__ void __launch_bounds__(256) qknew_kernel(
    const float* __restrict__ qin, const float* __restrict__ kin,
    const float* __restrict__ Wqo, const float* __restrict__ bqo,
    const float* __restrict__ Wko, const float* __restrict__ bko,
    const float* __restrict__ qg,  const float* __restrict__ qb,
    const float* __restrict__ kg,  const float* __restrict__ kb,
    float* __restrict__ out)
{
    extern __shared__ float sm[];
    float* s_flat = sm;
    float* Wsm    = sm + 16 * 512;
    float* zs     = Wsm + 64 * 129;
    float* mn     = zs + 16 * 64;
    float* rs     = mn + 16;

    const float* proj; const float* W; const float* bo; const float* xin;
    const float* g; const float* bt; float* o;
    if (blockIdx.y == 0) { proj = g_pq; W = Wqo; bo = bqo; xin = qin; g = qg; bt = qb; o = out; }
    else                 { proj = g_pk; W = Wko; bo = bko; xin = kin; g = kg; bt = kb; o = out + N_TOK * QDIM; }

    int n0 = blockIdx.x * 16;
    int t  = threadIdx.x;
    int oi = t & 63;
    int rseg = t >> 6;

    #pragma unroll
    for (int i = t; i < 16 * 128; i += 256)
        ((float4*)s_flat)[i] = ((const float4*)proj)[n0 * 128 + i];
    __syncthreads();

    float acc[4] = {0.f, 0.f, 0.f, 0.f};
    for (int jc = 0; jc < 4; jc++) {
        __syncthreads();
        #pragma unroll
        for (int i = t; i < 64 * 32; i += 256) {
            int oo = i >> 5, c4 = i & 31;
            float4 w = ((const float4*)W)[oo * 128 + jc * 32 + c4];
            float* dst = Wsm + oo * 129 + c4 * 4;
            dst[0] = w.x; dst[1] = w.y; dst[2] = w.z; dst[3] = w.w;
        }
        __syncthreads();
        #pragma unroll 4
        for (int jj = 0; jj < 128; jj++) {
            int j = jc * 128 + jj;
            int pidx = (j & 3) * 128 + (j >> 2);
            float w = Wsm[oi * 129 + jj];
            #pragma unroll
            for (int i = 0; i < 4; i++)
                acc[i] += s_flat[(rseg * 4 + i) * 512 + pidx] * w;
        }
    }

    #pragma unroll
    for (int i = 0; i < 4; i++) {
        int r = rseg * 4 + i;
        float x = acc[i] + bo[oi];
        zs[r * 64 + oi] = xin[(n0 + r) * QDIM + oi] + mishf(x);
    }
    __syncthreads();
    if (t < 16) {
        float s = 0.f;
        for (int c = 0; c < 64; c++) s += zs[t * 64 + c];
        float mean = s * (1.f / 64.f);
        float v2 = 0.f;
        for (int c = 0; c < 64; c++) { float d = zs[t * 64 + c] - mean; v2 += d * d; }
        mn[t] = mean;
        rs[t] = rsqrtf(v2 * (1.f / 64.f) + 1e-5f);
    }
    __syncthreads();
    #pragma unroll
    for (int i = 0; i < 4; i++) {
        int r = rseg * 4 + i;
        float zz = zs[r * 64 + oi];
        o[(n0 + r) * QDIM + oi] = (zz - mn[r]) * rs[r] * g[oi] + bt[oi];
    }
}

// =====================================================================
// launch
// =====================================================================
extern "C" void kernel_launch(void* const* d_in, const int* in_sizes, int n_in,
                              void* d_out, int out_size)
{
    const float* q    = (const float*)d_in[0];
    const float* k    = (const float*)d_in[1];
    const float* v    = (const float*)d_in[2];
    const float* bias = (const float*)d_in[3];
    const float* Wq   = (const float*)d_in[4];
    const float* bq   = (const float*)d_in[5];
    const float* Wk   = (const float*)d_in[6];
    const float* bk   = (const float*)d_in[7];
    const float* Wqo  = (const float*)d_in[8];
    const float* bqo  = (const float*)d_in[9];
    const float* Wko  = (const float*)d_in[10];
    const float* bko  = (const float*)d_in[11];
    const float* qg   = (const float*)d_in[12];
    const float* qb   = (const float*)d_in[13];
    const float* kg   = (const float*)d_in[14];
    const float* kb   = (const float*)d_in[15];
    const float* Wb   = (const float*)d_in[16];
    const float* bb   = (const float*)d_in[17];
    const float* Wbo  = (const float*)d_in[18];
    const float* bbo  = (const float*)d_in[19];

    float* out       = (float*)d_out;
    float* out_vals  = out + 2 * N_TOK * QDIM;
    float* out_bias  = out_vals + N_TOK;

    const int SMEM2 = (16 * 512 + 64 * 129 + 16 * 64 + 32) * 4;
    cudaFuncSetAttribute(bias_fused_mma, cudaFuncAttributeMaxDynamicSharedMemorySize, SM_TOT);
    cudaFuncSetAttribute(qknew_kernel,   cudaFuncAttributeMaxDynamicSharedMemorySize, SMEM2);

    prep_split<<<(HBD * BD + 255) / 256, 256>>>(Wb, Wbo);
    proj_kernel<<<dim3(N_TOK, 2), 256>>>(q, Wq, bq, k, Wk, bk);

    bias_fused_mma<<<NN / 128, 512, SM_TOT>>>(bias, bb, bbo, out_bias);

    logits_kernel<<<dim3(N_TOK / 16, H_HEADS, 8), 256>>>();
    softmax_v_kernel<<<H_HEADS * N_TOK, 256>>>(v);
    mean_kernel<<<1, N_TOK>>>(out_vals);
    qknew_kernel<<<dim3(N_TOK / 16, 2), 256, SMEM2>>>(
        q, k, Wqo, bqo, Wko, bko, qg, qb, kg, kb, out);
}

// round 6
// speedup vs baseline: 2.9015x; 1.1608x over previous
#include <cuda_runtime.h>
#include <cuda_bf16.h>
#include <cuda_fp16.h>
#include <math.h>
#include <stdint.h>

// ---- problem constants ----
#define N_TOK   512
#define QDIM    64
#define H_HEADS 4
#define D_HEAD  128
#define HD      512
#define BD      128
#define HBD     512
#define NN      (N_TOK * N_TOK)
#define INV_SQRT_D 0.08838834764831845f

// ---- scratch globals ----
__device__ float g_pq[N_TOK * HD];
__device__ float g_pk[N_TOK * HD];
__device__ float g_diffs[H_HEADS * NN];
__device__ float g_logits[H_HEADS * NN];
__device__ float g_val[H_HEADS * N_TOK];
// pre-split weights (fp16 hi/lo). Wbo reordered chunk-major: [nc][o][jj]
__device__ __half g_Wb_hi[HBD * BD];
__device__ __half g_Wb_lo[HBD * BD];
__device__ __half g_Wbo_hi[H_HEADS * BD * BD];
__device__ __half g_Wbo_lo[H_HEADS * BD * BD];

__device__ __forceinline__ float mishf(float x) {
    float sp = (x > 20.f) ? x : log1pf(expf(x));
    return x * tanhf(sp);
}
static __device__ __forceinline__ uint32_t pk2h(__half a, __half b) {
    return (uint32_t)__half_as_ushort(a) | ((uint32_t)__half_as_ushort(b) << 16);
}

// warp-level fp16 MMA (sm_80+ PTX; works on bare sm_103 target)
static __device__ __forceinline__ void mma16816(float* d, const uint32_t* a,
                                                uint32_t b0, uint32_t b1) {
    asm volatile(
        "mma.sync.aligned.m16n8k16.row.col.f32.f16.f16.f32 "
        "{%0,%1,%2,%3}, {%4,%5,%6,%7}, {%8,%9}, {%0,%1,%2,%3};"
        : "+f"(d[0]), "+f"(d[1]), "+f"(d[2]), "+f"(d[3])
        : "r"(a[0]), "r"(a[1]), "r"(a[2]), "r"(a[3]), "r"(b0), "r"(b1));
}

// smem layout (bytes)
#define SMA     0          // A frags (single fp16)     32 KB
#define SMW_HI  32768      // W hi frags                32 KB
#define SMW_LO  65536      // W lo frags                32 KB
#define SMP     98304      // P frags (single fp16)     32 KB
#define SM_BB   131072
#define SM_BBO  133120
#define SM_PART 133632
#define SM_TOT  134656

// =====================================================================
// Kernel 0: pre-split Wb / Wbo into fp16 hi/lo (Wbo chunk-major reorder)
// =====================================================================
__global__ void __launch_bounds__(256) prep_split(const float* __restrict__ Wb,
                                                  const float* __restrict__ Wbo)
{
    int i = blockIdx.x * 256 + threadIdx.x;
    if (i < HBD * BD) {
        float w = Wb[i];
        __half h = __float2half(w);
        g_Wb_hi[i] = h;
        g_Wb_lo[i] = __float2half(w - __half2float(h));

        int o = i >> 9, j = i & 511;          // Wbo[o][j]
        int nc = j >> 7, jj = j & 127;
        float w2 = Wbo[i];
        __half h2 = __float2half(w2);
        int dst = nc * (BD * BD) + o * BD + jj;
        g_Wbo_hi[dst] = h2;
        g_Wbo_lo[dst] = __float2half(w2 - __half2float(h2));
    }
}

// =====================================================================
// Kernel 1: q/k projections
// =====================================================================
__global__ void __launch_bounds__(256) proj_kernel(
    const float* __restrict__ q,  const float* __restrict__ Wq, const float* __restrict__ bq,
    const float* __restrict__ k,  const float* __restrict__ Wk, const float* __restrict__ bk)
{
    const float* x; const float* W; const float* b; float* out;
    if (blockIdx.y == 0) { x = q; W = Wq; b = bq; out = g_pq; }
    else                 { x = k; W = Wk; b = bk; out = g_pk; }
    int n = blockIdx.x;
    int t = threadIdx.x;
    __shared__ float xs[QDIM];
    if (t < QDIM/4) ((float4*)xs)[t] = ((const float4*)(x + n * QDIM))[t];
    __syncthreads();
    for (int j = t; j < HD; j += 256) {
        float s = b[j];
        const float4* wr = (const float4*)(W + j * QDIM);
        #pragma unroll
        for (int c = 0; c < QDIM/4; c++) {
            float4 w = wr[c];
            s += xs[4*c+0]*w.x + xs[4*c+1]*w.y + xs[4*c+2]*w.z + xs[4*c+3]*w.w;
        }
        out[n * HD + j] = s;
    }
}

// =====================================================================
// Kernel 2: fused bias pipeline on warp MMA (FP16x2: weights split hi/lo,
// activations single fp16).
// 512 threads, 16 warps. Warp (m = w&7, nh = w>>3):
//   rows 16m..16m+15, output cols nh*64..+63.
// P exchanged through SMEM in A-fragment layout (D-frag == A-frag bitwise).
// Frag layouts:
//   A/P buf: [mtile 8][ks 8][reg 4][lane 32] uint32
//   W buf:   [ntile 16][ks 8][reg 2][lane 32] uint32 (hi & lo)
// =====================================================================
__global__ void __launch_bounds__(512, 1) bias_fused_mma(
    const float* __restrict__ bias, const float* __restrict__ bb,
    const float* __restrict__ bbo,  float* __restrict__ bias_out)
{
    extern __shared__ char smc[];
    uint32_t* Af  = (uint32_t*)(smc + SMA);
    uint32_t* Whi = (uint32_t*)(smc + SMW_HI);
    uint32_t* Wlo = (uint32_t*)(smc + SMW_LO);
    uint32_t* Pf  = (uint32_t*)(smc + SMP);
    float*    bb_s  = (float*)(smc + SM_BB);
    float*    bbo_s = (float*)(smc + SM_BBO);
    float*    part  = (float*)(smc + SM_PART);

    int t = threadIdx.x, wid = t >> 5, lane = t & 31;
    int gq = lane >> 2, tt = lane & 3;
    int m  = wid & 7;         // row-tile (16 rows)
    int nh = wid >> 3;        // column half (0: cols 0-63, 1: cols 64-127)
    int m0 = blockIdx.x * 128;

    if (t < 128) bbo_s[t] = bbo[t];
    if (t < 512) bb_s[t] = bb[t];

    // ---- stage bias tile -> A frag buffer (single fp16) ----
    {
        const float4* src = (const float4*)(bias + (size_t)m0 * BD);
        #pragma unroll
        for (int i = t; i < 4096; i += 512) {
            int r = i >> 5, c = (i & 31) << 2;
            float4 v = src[i];
            int mt = r >> 4, g = r & 15, ks = c >> 4, cl = c & 15;
            int reg = ((cl >= 8) ? 2 : 0) + ((g >= 8) ? 1 : 0);
            int ln0 = (g & 7) * 4 + ((cl & 7) >> 1);
            int idx = ((mt * 8 + ks) * 4 + reg) * 32 + ln0;
            *(uint2*)(Af + idx) = make_uint2(
                pk2h(__float2half(v.x), __float2half(v.y)),
                pk2h(__float2half(v.z), __float2half(v.w)));
        }
    }

    float O[8][4];
    #pragma unroll
    for (int j = 0; j < 8; j++)
        #pragma unroll
        for (int r = 0; r < 4; r++) O[j][r] = 0.f;

    for (int nc = 0; nc < 4; nc++) {
        __syncthreads();   // previous readers of W/P buffers done
        // ---- stage Wb chunk (hi/lo) ----
        {
            const uint4* sh = (const uint4*)(g_Wb_hi + nc * (BD * BD));
            const uint4* sl = (const uint4*)(g_Wb_lo + nc * (BD * BD));
            #pragma unroll
            for (int i = t; i < 2048; i += 512) {
                int n = i >> 4, k8 = i & 15;
                int nt = n >> 3, g = n & 7, ks = k8 >> 1, reg = k8 & 1;
                int idx = (((nt * 8 + ks) * 2 + reg) * 32 + g * 4);
                *(uint4*)(Whi + idx) = sh[i];
                *(uint4*)(Wlo + idx) = sl[i];
            }
        }
        __syncthreads();

        // ---- GEMM1: D1 = A @ (Whi+Wlo)^T (2-pass fp16), 64 cols per warp ----
        float D1[8][4];
        #pragma unroll
        for (int j = 0; j < 8; j++)
            #pragma unroll
            for (int r = 0; r < 4; r++) D1[j][r] = 0.f;

        #pragma unroll
        for (int ks = 0; ks < 8; ks++) {
            uint32_t a[4];
            int ab = (m * 8 + ks) * 128;
            #pragma unroll
            for (int r = 0; r < 4; r++) a[r] = Af[ab + r * 32 + lane];
            #pragma unroll
            for (int j = 0; j < 8; j++) {
                int jt = nh * 8 + j;
                int wb = ((jt * 8 + ks) * 2) * 32 + lane;
                uint32_t b0h = Whi[wb], b1h = Whi[wb + 32];
                uint32_t b0l = Wlo[wb], b1l = Wlo[wb + 32];
                mma16816(D1[j], a, b0h, b1h);
                mma16816(D1[j], a, b0l, b1l);
            }
        }

        // ---- convert: P = D1 + bb -> fp16 -> SMEM P frags; norms ----
        float sqlo = 0.f, sqhi = 0.f;
        #pragma unroll
        for (int j = 0; j < 8; j++) {
            int jt = nh * 8 + j;
            float b0 = bb_s[nc * 128 + jt * 8 + 2 * tt];
            float b1 = bb_s[nc * 128 + jt * 8 + 2 * tt + 1];
            float p0 = D1[j][0] + b0, p1 = D1[j][1] + b1;
            float p2 = D1[j][2] + b0, p3 = D1[j][3] + b1;
            sqlo += p0 * p0 + p1 * p1;
            sqhi += p2 * p2 + p3 * p3;
            // D-frag == A-frag: rows g -> reg (hi8*2), rows g+8 -> reg (hi8*2+1)
            int s = jt >> 1, hi8 = jt & 1;
            int i0 = ((m * 8 + s) * 4 + hi8 * 2) * 32 + lane;
            Pf[i0]      = pk2h(__float2half(p0), __float2half(p1));
            Pf[i0 + 32] = pk2h(__float2half(p2), __float2half(p3));
        }
        sqlo += __shfl_xor_sync(0xFFFFFFFF, sqlo, 1);
        sqlo += __shfl_xor_sync(0xFFFFFFFF, sqlo, 2);
        sqhi += __shfl_xor_sync(0xFFFFFFFF, sqhi, 1);
        sqhi += __shfl_xor_sync(0xFFFFFFFF, sqhi, 2);
        if (tt == 0) {
            part[nh * 128 + m * 16 + gq]     = sqlo;
            part[nh * 128 + m * 16 + gq + 8] = sqhi;
        }

        __syncthreads();   // P frags + norm partials complete; Wb reads done

        // ---- combine norms; stage Wbo chunk ----
        if (t < 128)
            g_diffs[(size_t)nc * NN + m0 + t] = sqrtf(part[t] + part[128 + t]);
        {
            const uint4* sh = (const uint4*)(g_Wbo_hi + nc * (BD * BD));
            const uint4* sl = (const uint4*)(g_Wbo_lo + nc * (BD * BD));
            #pragma unroll
            for (int i = t; i < 2048; i += 512) {
                int n = i >> 4, k8 = i & 15;
                int nt = n >> 3, g = n & 7, ks = k8 >> 1, reg = k8 & 1;
                int idx = (((nt * 8 + ks) * 2 + reg) * 32 + g * 4);
                *(uint4*)(Whi + idx) = sh[i];
                *(uint4*)(Wlo + idx) = sl[i];
            }
        }
        __syncthreads();

        // ---- GEMM2: O += P @ (Whi+Wlo)^T (2-pass fp16) ----
        #pragma unroll
        for (int ks = 0; ks < 8; ks++) {
            uint32_t p[4];
            int pb = (m * 8 + ks) * 128;
            #pragma unroll
            for (int r = 0; r < 4; r++) p[r] = Pf[pb + r * 32 + lane];
            #pragma unroll
            for (int j = 0; j < 8; j++) {
                int jt = nh * 8 + j;
                int wb = ((jt * 8 + ks) * 2) * 32 + lane;
                uint32_t b0h = Whi[wb], b1h = Whi[wb + 32];
                uint32_t b0l = Wlo[wb], b1l = Wlo[wb + 32];
                mma16816(O[j], p, b0h, b1h);
                mma16816(O[j], p, b0l, b1l);
            }
        }
    }

    // ---- final: O + bbo, mish -> gmem ----
    int row = m0 + m * 16 + gq;
    #pragma unroll
    for (int j = 0; j < 8; j++) {
        int col = nh * 64 + j * 8 + 2 * tt;
        float b0 = bbo_s[col], b1 = bbo_s[col + 1];
        float2 v0, v1;
        v0.x = mishf(O[j][0] + b0);  v0.y = mishf(O[j][1] + b1);
        v1.x = mishf(O[j][2] + b0);  v1.y = mishf(O[j][3] + b1);
        *(float2*)(bias_out + (size_t)row * BD + col)       = v0;
        *(float2*)(bias_out + (size_t)(row + 8) * BD + col) = v1;
    }
}

// =====================================================================
// Kernel 3: logits  (parallel over k-chunks: grid (32, 4, 8))
// =====================================================================
__global__ void __launch_bounds__(256) logits_kernel()
{
    __shared__ float pq_s[16 * 128];
    __shared__ float pk_s[64 * 129];
    int q0 = blockIdx.x * 16;
    int h  = blockIdx.y;
    int kc = blockIdx.z;
    int t  = threadIdx.x;
    int qi = t >> 4;
    int kx = t & 15;

    #pragma unroll
    for (int i = t; i < 16 * 32; i += 256) {
        int r = i >> 5, c4 = i & 31;
        ((float4*)pq_s)[r * 32 + c4] = ((const float4*)g_pq)[(q0 + r) * 128 + h * 32 + c4];
    }
    #pragma unroll
    for (int i = t; i < 64 * 32; i += 256) {
        int r = i >> 5, c4 = i & 31;
        float4 w = ((const float4*)g_pk)[(kc * 64 + r) * 128 + h * 32 + c4];
        float* dst = pk_s + r * 129 + c4 * 4;
        dst[0] = w.x; dst[1] = w.y; dst[2] = w.z; dst[3] = w.w;
    }
    __syncthreads();

    float acc0 = 0, acc1 = 0, acc2 = 0, acc3 = 0;
    const float* ap = pq_s + qi * 128;
    const float* k0 = pk_s + (kx * 4    ) * 129;
    const float* k1 = pk_s + (kx * 4 + 1) * 129;
    const float* k2 = pk_s + (kx * 4 + 2) * 129;
    const float* k3 = pk_s + (kx * 4 + 3) * 129;
    #pragma unroll 8
    for (int d = 0; d < 128; d++) {
        float a = ap[d];
        acc0 += a * k0[d]; acc1 += a * k1[d];
        acc2 += a * k2[d]; acc3 += a * k3[d];
    }
    size_t base = (size_t)h * NN + (size_t)(q0 + qi) * N_TOK + kc * 64 + kx * 4;
    float4 dsum = *(const float4*)(g_diffs + base);
    float4 o;
    o.x = acc0 * INV_SQRT_D + dsum.x;
    o.y = acc1 * INV_SQRT_D + dsum.y;
    o.z = acc2 * INV_SQRT_D + dsum.z;
    o.w = acc3 * INV_SQRT_D + dsum.w;
    *(float4*)(g_logits + base) = o;
}

// =====================================================================
// Kernel 4: softmax + v
// =====================================================================
__global__ void __launch_bounds__(256) softmax_v_kernel(const float* __restrict__ v)
{
    __shared__ float r1[256];
    __shared__ float r2[256];
    int hq = blockIdx.x;
    int t  = threadIdx.x;
    const float* lr = g_logits + (size_t)hq * N_TOK;
    float l0 = lr[t], l1 = lr[t + 256];
    float m = fmaxf(l0, l1);
    r1[t] = m;
    __syncthreads();
    #pragma unroll
    for (int s = 128; s > 0; s >>= 1) {
        if (t < s) r1[t] = fmaxf(r1[t], r1[t + s]);
        __syncthreads();
    }
    m = r1[0];
    __syncthreads();
    float e0 = expf(l0 - m), e1 = expf(l1 - m);
    r1[t] = e0 + e1;
    r2[t] = e0 * v[t] + e1 * v[t + 256];
    __syncthreads();
    #pragma unroll
    for (int s = 128; s > 0; s >>= 1) {
        if (t < s) { r1[t] += r1[t + s]; r2[t] += r2[t + s]; }
        __syncthreads();
    }
    if (t == 0) g_val[hq] = r2[0] / r1[0];
}

__global__ void mean_kernel(float* __restrict__ out)
{
    int t = threadIdx.x;
    out[t] = 0.25f * (g_val[t] + g_val[N_TOK + t] + g_val[2 * N_TOK + t] + g_val[3 * N_TOK + t]);
}

// =====================================================================
// Kernel 6: q_new / k_new heads
// =====================================================================
__global__ void __launch_bounds__(256) qknew_kernel(
    const float* __restrict__ qin, const float* __restrict__ kin,
    const float* __restrict__ Wqo, const float* __restrict__ bqo,
    const float* __restrict__ Wko, const float* __restrict__ bko,
    const float* __restrict__ qg,  const float* __restrict__ qb,
    const float* __restrict__ kg,  const float* __restrict__ kb,
    float* __restrict__ out)
{
    extern __shared__ float sm[];
    float* s_flat = sm;
    float* Wsm    = sm + 16 * 512;
    float* zs     = Wsm + 64 * 129;
    float* mn     = zs + 16 * 64;
    float* rs     = mn + 16;

    const float* proj; const float* W; const float* bo; const float* xin;
    const float* g; const float* bt; float* o;
    if (blockIdx.y == 0) { proj = g_pq; W = Wqo; bo = bqo; xin = qin; g = qg; bt = qb; o = out; }
    else                 { proj = g_pk; W = Wko; bo = bko; xin = kin; g = kg; bt = kb; o = out + N_TOK * QDIM; }

    int n0 = blockIdx.x * 16;
    int t  = threadIdx.x;
    int oi = t & 63;
    int rseg = t >> 6;

    #pragma unroll
    for (int i = t; i < 16 * 128; i += 256)
        ((float4*)s_flat)[i] = ((const float4*)proj)[n0 * 128 + i];
    __syncthreads();

    float acc[4] = {0.f, 0.f, 0.f, 0.f};
    for (int jc = 0; jc < 4; jc++) {
        __syncthreads();
        #pragma unroll
        for (int i = t; i < 64 * 32; i += 256) {
            int oo = i >> 5, c4 = i & 31;
            float4 w = ((const float4*)W)[oo * 128 + jc * 32 + c4];
            float* dst = Wsm + oo * 129 + c4 * 4;
            dst[0] = w.x; dst[1] = w.y; dst[2] = w.z; dst[3] = w.w;
        }
        __syncthreads();
        #pragma unroll 4
        for (int jj = 0; jj < 128; jj++) {
            int j = jc * 128 + jj;
            int pidx = (j & 3) * 128 + (j >> 2);
            float w = Wsm[oi * 129 + jj];
            #pragma unroll
            for (int i = 0; i < 4; i++)
                acc[i] += s_flat[(rseg * 4 + i) * 512 + pidx] * w;
        }
    }

    #pragma unroll
    for (int i = 0; i < 4; i++) {
        int r = rseg * 4 + i;
        float x = acc[i] + bo[oi];
        zs[r * 64 + oi] = xin[(n0 + r) * QDIM + oi] + mishf(x);
    }
    __syncthreads();
    if (t < 16) {
        float s = 0.f;
        for (int c = 0; c < 64; c++) s += zs[t * 64 + c];
        float mean = s * (1.f / 64.f);
        float v2 = 0.f;
        for (int c = 0; c < 64; c++) { float d = zs[t * 64 + c] - mean; v2 += d * d; }
        mn[t] = mean;
        rs[t] = rsqrtf(v2 * (1.f / 64.f) + 1e-5f);
    }
    __syncthreads();
    #pragma unroll
    for (int i = 0; i < 4; i++) {
        int r = rseg * 4 + i;
        float zz = zs[r * 64 + oi];
        o[(n0 + r) * QDIM + oi] = (zz - mn[r]) * rs[r] * g[oi] + bt[oi];
    }
}

// =====================================================================
// launch
// =====================================================================
extern "C" void kernel_launch(void* const* d_in, const int* in_sizes, int n_in,
                              void* d_out, int out_size)
{
    const float* q    = (const float*)d_in[0];
    const float* k    = (const float*)d_in[1];
    const float* v    = (const float*)d_in[2];
    const float* bias = (const float*)d_in[3];
    const float* Wq   = (const float*)d_in[4];
    const float* bq   = (const float*)d_in[5];
    const float* Wk   = (const float*)d_in[6];
    const float* bk   = (const float*)d_in[7];
    const float* Wqo  = (const float*)d_in[8];
    const float* bqo  = (const float*)d_in[9];
    const float* Wko  = (const float*)d_in[10];
    const float* bko  = (const float*)d_in[11];
    const float* qg   = (const float*)d_in[12];
    const float* qb   = (const float*)d_in[13];
    const float* kg   = (const float*)d_in[14];
    const float* kb   = (const float*)d_in[15];
    const float* Wb   = (const float*)d_in[16];
    const float* bb   = (const float*)d_in[17];
    const float* Wbo  = (const float*)d_in[18];
    const float* bbo  = (const float*)d_in[19];

    float* out       = (float*)d_out;
    float* out_vals  = out + 2 * N_TOK * QDIM;
    float* out_bias  = out_vals + N_TOK;

    const int SMEM2 = (16 * 512 + 64 * 129 + 16 * 64 + 32) * 4;
    cudaFuncSetAttribute(bias_fused_mma, cudaFuncAttributeMaxDynamicSharedMemorySize, SM_TOT);
    cudaFuncSetAttribute(qknew_kernel,   cudaFuncAttributeMaxDynamicSharedMemorySize, SMEM2);

    prep_split<<<(HBD * BD + 255) / 256, 256>>>(Wb, Wbo);
    proj_kernel<<<dim3(N_TOK, 2), 256>>>(q, Wq, bq, k, Wk, bk);

    bias_fused_mma<<<NN / 128, 512, SM_TOT>>>(bias, bb, bbo, out_bias);

    logits_kernel<<<dim3(N_TOK / 16, H_HEADS, 8), 256>>>();
    softmax_v_kernel<<<H_HEADS * N_TOK, 256>>>(v);
    mean_kernel<<<1, N_TOK>>>(out_vals);
    qknew_kernel<<<dim3(N_TOK / 16, 2), 256, SMEM2>>>(
        q, k, Wqo, bqo, Wko, bko, qg, qb, kg, kb, out);
}

// round 15
// speedup vs baseline: 4.7632x; 1.6417x over previous
#include <cuda_runtime.h>
#include <cuda_bf16.h>
#include <cuda_fp16.h>
#include <math.h>
#include <stdint.h>

// ---- problem constants ----
#define N_TOK   512
#define QDIM    64
#define H_HEADS 4
#define D_HEAD  128
#define HD      512
#define BD      128
#define HBD     512
#define NN      (N_TOK * N_TOK)
#define INV_SQRT_D 0.08838834764831845f

// ---- scratch globals ----
__device__ float g_pq[N_TOK * HD];
__device__ float g_pk[N_TOK * HD];
__device__ float g_diffs[H_HEADS * NN];
__device__ float g_logits[H_HEADS * NN];
__device__ float g_val[H_HEADS * N_TOK];
// weights pre-converted to fp16 MMA B-fragment order: [nc][8192] u32
// (128x128 fp16 chunk = 16384 halves = 8192 u32 — round-9..11 sized this 4096: THE bug)
__device__ uint32_t g_Wbf_hi[H_HEADS * 8192];
__device__ uint32_t g_Wbf_lo[H_HEADS * 8192];
__device__ uint32_t g_Wbof[H_HEADS * 8192];

// fast mish: mish(x) = x * tanh(softplus(x)) = x * u/(u+2), u = e^x(e^x+2)
__device__ __forceinline__ float mishf(float x) {
    float xc = fminf(x, 15.f);
    float e = __expf(xc);
    float u = e * (e + 2.f);
    return x * (u / (u + 2.f));
}
static __device__ __forceinline__ uint32_t pk2h(__half a, __half b) {
    return (uint32_t)__half_as_ushort(a) | ((uint32_t)__half_as_ushort(b) << 16);
}

// warp-level fp16 MMA (sm_80+ PTX; works on bare sm_103 target)
static __device__ __forceinline__ void mma16816(float* d, const uint32_t* a,
                                                uint32_t b0, uint32_t b1) {
    asm volatile(
        "mma.sync.aligned.m16n8k16.row.col.f32.f16.f16.f32 "
        "{%0,%1,%2,%3}, {%4,%5,%6,%7}, {%8,%9}, {%0,%1,%2,%3};"
        : "+f"(d[0]), "+f"(d[1]), "+f"(d[2]), "+f"(d[3])
        : "r"(a[0]), "r"(a[1]), "r"(a[2]), "r"(a[3]), "r"(b0), "r"(b1));
}

// B-frag u32 index for element (n, k) within a 128x128 chunk; range 0..8191
static __device__ __forceinline__ int bfrag_idx(int n, int k) {
    return (((n >> 3) * 8 + (k >> 4)) * 2 + ((k >> 3) & 1)) * 32 + (n & 7) * 4 + ((k & 7) >> 1);
}

// smem layout (bytes)
#define SMA      0          // A frags (fp16)       32 KB
#define SMWB_HI  32768      // Wb hi frags          32 KB
#define SMWB_LO  65536      // Wb lo frags          32 KB
#define SMWO     98304      // Wbo frags            32 KB
#define SMP      131072     // P frags (fp16)       32 KB
#define SM_BB    163840
#define SM_BBO   165888
#define SM_PART  166400
#define SM_TOT   167424

// =====================================================================
// Kernel 0: pre-convert Wb (hi/lo) / Wbo (single) to fp16 fragment order
// =====================================================================
__global__ void __launch_bounds__(256) prep_split(const float* __restrict__ Wb,
                                                  const float* __restrict__ Wbo)
{
    int i = blockIdx.x * 256 + threadIdx.x;   // 0..32767
    {
        // Wb[R (0..511)][k (0..127)] ; chunk nc = R>>7, n = R&127
        int R = i >> 6, k = (i & 63) * 2;
        int nc = R >> 7, n = R & 127;
        float w0 = Wb[R * 128 + k], w1 = Wb[R * 128 + k + 1];
        __half h0 = __float2half(w0), h1 = __float2half(w1);
        int idx = nc * 8192 + bfrag_idx(n, k);
        g_Wbf_hi[idx] = pk2h(h0, h1);
        g_Wbf_lo[idx] = pk2h(__float2half(w0 - __half2float(h0)),
                             __float2half(w1 - __half2float(h1)));
    }
    {
        // Wbo[o (0..127)][col (0..511)] ; chunk nc = col>>7 ; n = o, k = col&127
        int nc = i >> 13, rem = i & 8191;
        int o = rem >> 6, jj = (rem & 63) * 2;
        float w0 = Wbo[o * 512 + nc * 128 + jj], w1 = Wbo[o * 512 + nc * 128 + jj + 1];
        g_Wbof[nc * 8192 + bfrag_idx(o, jj)] = pk2h(__float2half(w0), __float2half(w1));
    }
}

// =====================================================================
// Kernel 1: q/k projections
// =====================================================================
__global__ void __launch_bounds__(256) proj_kernel(
    const float* __restrict__ q,  const float* __restrict__ Wq, const float* __restrict__ bq,
    const float* __restrict__ k,  const float* __restrict__ Wk, const float* __restrict__ bk)
{
    const float* x; const float* W; const float* b; float* out;
    if (blockIdx.y == 0) { x = q; W = Wq; b = bq; out = g_pq; }
    else                 { x = k; W = Wk; b = bk; out = g_pk; }
    int n = blockIdx.x;
    int t = threadIdx.x;
    __shared__ float xs[QDIM];
    if (t < QDIM/4) ((float4*)xs)[t] = ((const float4*)(x + n * QDIM))[t];
    __syncthreads();
    for (int j = t; j < HD; j += 256) {
        float s = b[j];
        const float4* wr = (const float4*)(W + j * QDIM);
        #pragma unroll
        for (int c = 0; c < QDIM/4; c++) {
            float4 w = wr[c];
            s += xs[4*c+0]*w.x + xs[4*c+1]*w.y + xs[4*c+2]*w.z + xs[4*c+3]*w.w;
        }
        out[n * HD + j] = s;
    }
}

// =====================================================================
// Kernel 2: fused bias pipeline.
// GEMM1: fp16x2 (weights hi/lo) — feeds diffs (softmax-sensitive path).
// GEMM2: fp16x1 — bias_out only (no amplification).
// 512 threads, 16 warps. Warp (m = w&7, nh = w>>3):
//   rows 16m..16m+15, output cols nh*64..+63.
// =====================================================================
__global__ void __launch_bounds__(512, 1) bias_fused_mma(
    const float* __restrict__ bias, const float* __restrict__ bb,
    const float* __restrict__ bbo,  float* __restrict__ bias_out)
{
    extern __shared__ char smc[];
    uint32_t* Af  = (uint32_t*)(smc + SMA);
    uint32_t* Wbh = (uint32_t*)(smc + SMWB_HI);
    uint32_t* Wbl = (uint32_t*)(smc + SMWB_LO);
    uint32_t* Wof = (uint32_t*)(smc + SMWO);
    uint32_t* Pf  = (uint32_t*)(smc + SMP);
    float*    bb_s  = (float*)(smc + SM_BB);
    float*    bbo_s = (float*)(smc + SM_BBO);
    float*    part  = (float*)(smc + SM_PART);

    int t = threadIdx.x, wid = t >> 5, lane = t & 31;
    int gq = lane >> 2, tt = lane & 3;
    int m  = wid & 7;         // row-tile (16 rows)
    int nh = wid >> 3;        // column half
    int m0 = blockIdx.x * 128;

    if (t < 128) bbo_s[t] = bbo[t];
    if (t < 512) bb_s[t] = bb[t];

    // ---- stage bias tile -> A frag buffer (fp16) ----
    {
        const float4* src = (const float4*)(bias + (size_t)m0 * BD);
        #pragma unroll
        for (int i = t; i < 4096; i += 512) {
            int r = i >> 5, c = (i & 31) << 2;
            float4 v = src[i];
            int mt = r >> 4, g = r & 15, ks = c >> 4, cl = c & 15;
            int reg = ((cl >= 8) ? 2 : 0) + ((g >= 8) ? 1 : 0);
            int ln0 = (g & 7) * 4 + ((cl & 7) >> 1);
            int idx = ((mt * 8 + ks) * 4 + reg) * 32 + ln0;
            *(uint2*)(Af + idx) = make_uint2(
                pk2h(__float2half(v.x), __float2half(v.y)),
                pk2h(__float2half(v.z), __float2half(v.w)));
        }
    }

    float O[8][4];
    #pragma unroll
    for (int j = 0; j < 8; j++)
        #pragma unroll
        for (int r = 0; r < 4; r++) O[j][r] = 0.f;

    for (int nc = 0; nc < 4; nc++) {
        __syncthreads();   // previous GEMM readers done with W/P buffers
        // ---- stage Wb hi/lo + Wbo chunks (2048 uint4 each = full 32 KB) ----
        {
            const uint4* sh = (const uint4*)(g_Wbf_hi + nc * 8192);
            const uint4* sl = (const uint4*)(g_Wbf_lo + nc * 8192);
            const uint4* so = (const uint4*)(g_Wbof   + nc * 8192);
            #pragma unroll
            for (int i = t; i < 2048; i += 512) {
                ((uint4*)Wbh)[i] = sh[i];
                ((uint4*)Wbl)[i] = sl[i];
                ((uint4*)Wof)[i] = so[i];
            }
        }
        __syncthreads();

        // ---- GEMM1: D1 = A @ (Wb_hi + Wb_lo)^T (2-pass fp16) ----
        float D1[8][4];
        #pragma unroll
        for (int j = 0; j < 8; j++)
            #pragma unroll
            for (int r = 0; r < 4; r++) D1[j][r] = 0.f;

        #pragma unroll
        for (int ks = 0; ks < 8; ks++) {
            uint32_t a[4];
            int ab = (m * 8 + ks) * 128;
            #pragma unroll
            for (int r = 0; r < 4; r++) a[r] = Af[ab + r * 32 + lane];
            #pragma unroll
            for (int j = 0; j < 8; j++) {
                int jt = nh * 8 + j;
                int wb = ((jt * 8 + ks) * 2) * 32 + lane;
                mma16816(D1[j], a, Wbh[wb], Wbh[wb + 32]);
                mma16816(D1[j], a, Wbl[wb], Wbl[wb + 32]);
            }
        }

        // ---- convert: P = D1 + bb -> fp16 -> SMEM P frags; norms (fp32) ----
        float sqlo = 0.f, sqhi = 0.f;
        #pragma unroll
        for (int j = 0; j < 8; j++) {
            int jt = nh * 8 + j;
            float b0 = bb_s[nc * 128 + jt * 8 + 2 * tt];
            float b1 = bb_s[nc * 128 + jt * 8 + 2 * tt + 1];
            float p0 = D1[j][0] + b0, p1 = D1[j][1] + b1;
            float p2 = D1[j][2] + b0, p3 = D1[j][3] + b1;
            sqlo += p0 * p0 + p1 * p1;
            sqhi += p2 * p2 + p3 * p3;
            // D-frag == A-frag layout
            int s = jt >> 1, hi8 = jt & 1;
            int i0 = ((m * 8 + s) * 4 + hi8 * 2) * 32 + lane;
            Pf[i0]      = pk2h(__float2half(p0), __float2half(p1));
            Pf[i0 + 32] = pk2h(__float2half(p2), __float2half(p3));
        }
        sqlo += __shfl_xor_sync(0xFFFFFFFF, sqlo, 1);
        sqlo += __shfl_xor_sync(0xFFFFFFFF, sqlo, 2);
        sqhi += __shfl_xor_sync(0xFFFFFFFF, sqhi, 1);
        sqhi += __shfl_xor_sync(0xFFFFFFFF, sqhi, 2);
        if (tt == 0) {
            part[nh * 128 + m * 16 + gq]     = sqlo;
            part[nh * 128 + m * 16 + gq + 8] = sqhi;
        }

        __syncthreads();   // P frags + norm partials complete

        // ---- combine norms ----
        if (t < 128)
            g_diffs[(size_t)nc * NN + m0 + t] = sqrtf(part[t] + part[128 + t]);

        // ---- GEMM2: O += P @ Wbo^T (1-pass fp16) ----
        #pragma unroll
        for (int ks = 0; ks < 8; ks++) {
            uint32_t p[4];
            int pb = (m * 8 + ks) * 128;
            #pragma unroll
            for (int r = 0; r < 4; r++) p[r] = Pf[pb + r * 32 + lane];
            #pragma unroll
            for (int j = 0; j < 8; j++) {
                int jt = nh * 8 + j;
                int wb = ((jt * 8 + ks) * 2) * 32 + lane;
                mma16816(O[j], p, Wof[wb], Wof[wb + 32]);
            }
        }
    }

    // ---- final: O + bbo, mish -> gmem ----
    int row = m0 + m * 16 + gq;
    #pragma unroll
    for (int j = 0; j < 8; j++) {
        int col = nh * 64 + j * 8 + 2 * tt;
        float b0 = bbo_s[col], b1 = bbo_s[col + 1];
        float2 v0, v1;
        v0.x = mishf(O[j][0] + b0);  v0.y = mishf(O[j][1] + b1);
        v1.x = mishf(O[j][2] + b0);  v1.y = mishf(O[j][3] + b1);
        *(float2*)(bias_out + (size_t)row * BD + col)       = v0;
        *(float2*)(bias_out + (size_t)(row + 8) * BD + col) = v1;
    }
}

// =====================================================================
// Kernel 3: logits  (parallel over k-chunks: grid (32, 4, 8))
// =====================================================================
__global__ void __launch_bounds__(256) logits_kernel()
{
    __shared__ float pq_s[16 * 128];
    __shared__ float pk_s[64 * 129];
    int q0 = blockIdx.x * 16;
    int h  = blockIdx.y;
    int kc = blockIdx.z;
    int t  = threadIdx.x;
    int qi = t >> 4;
    int kx = t & 15;

    #pragma unroll
    for (int i = t; i < 16 * 32; i += 256) {
        int r = i >> 5, c4 = i & 31;
        ((float4*)pq_s)[r * 32 + c4] = ((const float4*)g_pq)[(q0 + r) * 128 + h * 32 + c4];
    }
    #pragma unroll
    for (int i = t; i < 64 * 32; i += 256) {
        int r = i >> 5, c4 = i & 31;
        float4 w = ((const float4*)g_pk)[(kc * 64 + r) * 128 + h * 32 + c4];
        float* dst = pk_s + r * 129 + c4 * 4;
        dst[0] = w.x; dst[1] = w.y; dst[2] = w.z; dst[3] = w.w;
    }
    __syncthreads();

    float acc0 = 0, acc1 = 0, acc2 = 0, acc3 = 0;
    const float* ap = pq_s + qi * 128;
    const float* k0 = pk_s + (kx * 4    ) * 129;
    const float* k1 = pk_s + (kx * 4 + 1) * 129;
    const float* k2 = pk_s + (kx * 4 + 2) * 129;
    const float* k3 = pk_s + (kx * 4 + 3) * 129;
    #pragma unroll 8
    for (int d = 0; d < 128; d++) {
        float a = ap[d];
        acc0 += a * k0[d]; acc1 += a * k1[d];
        acc2 += a * k2[d]; acc3 += a * k3[d];
    }
    size_t base = (size_t)h * NN + (size_t)(q0 + qi) * N_TOK + kc * 64 + kx * 4;
    float4 dsum = *(const float4*)(g_diffs + base);
    float4 o;
    o.x = acc0 * INV_SQRT_D + dsum.x;
    o.y = acc1 * INV_SQRT_D + dsum.y;
    o.z = acc2 * INV_SQRT_D + dsum.z;
    o.w = acc3 * INV_SQRT_D + dsum.w;
    *(float4*)(g_logits + base) = o;
}

// =====================================================================
// Kernel 4: softmax + v
// =====================================================================
__global__ void __launch_bounds__(256) softmax_v_kernel(const float* __restrict__ v)
{
    __shared__ float r1[256];
    __shared__ float r2[256];
    int hq = blockIdx.x;
    int t  = threadIdx.x;
    const float* lr = g_logits + (size_t)hq * N_TOK;
    float l0 = lr[t], l1 = lr[t + 256];
    float m = fmaxf(l0, l1);
    r1[t] = m;
    __syncthreads();
    #pragma unroll
    for (int s = 128; s > 0; s >>= 1) {
        if (t < s) r1[t] = fmaxf(r1[t], r1[t + s]);
        __syncthreads();
    }
    m = r1[0];
    __syncthreads();
    float e0 = expf(l0 - m), e1 = expf(l1 - m);
    r1[t] = e0 + e1;
    r2[t] = e0 * v[t] + e1 * v[t + 256];
    __syncthreads();
    #pragma unroll
    for (int s = 128; s > 0; s >>= 1) {
        if (t < s) { r1[t] += r1[t + s]; r2[t] += r2[t + s]; }
        __syncthreads();
    }
    if (t == 0) g_val[hq] = r2[0] / r1[0];
}

__global__ void mean_kernel(float* __restrict__ out)
{
    int t = threadIdx.x;
    out[t] = 0.25f * (g_val[t] + g_val[N_TOK + t] + g_val[2 * N_TOK + t] + g_val[3 * N_TOK + t]);
}

// =====================================================================
// Kernel 6: q_new / k_new heads
// =====================================================================
__global__ void __launch_bounds__(256) qknew_kernel(
    const float* __restrict__ qin, const float* __restrict__ kin,
    const float* __restrict__ Wqo, const float* __restrict__ bqo,
    const float* __restrict__ Wko, const float* __restrict__ bko,
    const float* __restrict__ qg,  const float* __restrict__ qb,
    const float* __restrict__ kg,  const float* __restrict__ kb,
    float* __restrict__ out)
{
    extern __shared__ float sm[];
    float* s_flat = sm;
    float* Wsm    = sm + 16 * 512;
    float* zs     = Wsm + 64 * 129;
    float* mn     = zs + 16 * 64;
    float* rs     = mn + 16;

    const float* proj; const float* W; const float* bo; const float* xin;
    const float* g; const float* bt; float* o;
    if (blockIdx.y == 0) { proj = g_pq; W = Wqo; bo = bqo; xin = qin; g = qg; bt = qb; o = out; }
    else                 { proj = g_pk; W = Wko; bo = bko; xin = kin; g = kg; bt = kb; o = out + N_TOK * QDIM; }

    int n0 = blockIdx.x * 16;
    int t  = threadIdx.x;
    int oi = t & 63;
    int rseg = t >> 6;

    #pragma unroll
    for (int i = t; i < 16 * 128; i += 256)
        ((float4*)s_flat)[i] = ((const float4*)proj)[n0 * 128 + i];
    __syncthreads();

    float acc[4] = {0.f, 0.f, 0.f, 0.f};
    for (int jc = 0; jc < 4; jc++) {
        __syncthreads();
        #pragma unroll
        for (int i = t; i < 64 * 32; i += 256) {
            int oo = i >> 5, c4 = i & 31;
            float4 w = ((const float4*)W)[oo * 128 + jc * 32 + c4];
            float* dst = Wsm + oo * 129 + c4 * 4;
            dst[0] = w.x; dst[1] = w.y; dst[2] = w.z; dst[3] = w.w;
        }
        __syncthreads();
        #pragma unroll 4
        for (int jj = 0; jj < 128; jj++) {
            int j = jc * 128 + jj;
            int pidx = (j & 3) * 128 + (j >> 2);
            float w = Wsm[oi * 129 + jj];
            #pragma unroll
            for (int i = 0; i < 4; i++)
                acc[i] += s_flat[(rseg * 4 + i) * 512 + pidx] * w;
        }
    }

    #pragma unroll
    for (int i = 0; i < 4; i++) {
        int r = rseg * 4 + i;
        float x = acc[i] + bo[oi];
        zs[r * 64 + oi] = xin[(n0 + r) * QDIM + oi] + mishf(x);
    }
    __syncthreads();
    if (t < 16) {
        float s = 0.f;
        for (int c = 0; c < 64; c++) s += zs[t * 64 + c];
        float mean = s * (1.f / 64.f);
        float v2 = 0.f;
        for (int c = 0; c < 64; c++) { float d = zs[t * 64 + c] - mean; v2 += d * d; }
        mn[t] = mean;
        rs[t] = rsqrtf(v2 * (1.f / 64.f) + 1e-5f);
    }
    __syncthreads();
    #pragma unroll
    for (int i = 0; i < 4; i++) {
        int r = rseg * 4 + i;
        float zz = zs[r * 64 + oi];
        o[(n0 + r) * QDIM + oi] = (zz - mn[r]) * rs[r] * g[oi] + bt[oi];
    }
}

// =====================================================================
// launch
// =====================================================================
extern "C" void kernel_launch(void* const* d_in, const int* in_sizes, int n_in,
                              void* d_out, int out_size)
{
    const float* q    = (const float*)d_in[0];
    const float* k    = (const float*)d_in[1];
    const float* v    = (const float*)d_in[2];
    const float* bias = (const float*)d_in[3];
    const float* Wq   = (const float*)d_in[4];
    const float* bq   = (const float*)d_in[5];
    const float* Wk   = (const float*)d_in[6];
    const float* bk   = (const float*)d_in[7];
    const float* Wqo  = (const float*)d_in[8];
    const float* bqo  = (const float*)d_in[9];
    const float* Wko  = (const float*)d_in[10];
    const float* bko  = (const float*)d_in[11];
    const float* qg   = (const float*)d_in[12];
    const float* qb   = (const float*)d_in[13];
    const float* kg   = (const float*)d_in[14];
    const float* kb   = (const float*)d_in[15];
    const float* Wb   = (const float*)d_in[16];
    const float* bb   = (const float*)d_in[17];
    const float* Wbo  = (const float*)d_in[18];
    const float* bbo  = (const float*)d_in[19];

    float* out       = (float*)d_out;
    float* out_vals  = out + 2 * N_TOK * QDIM;
    float* out_bias  = out_vals + N_TOK;

    const int SMEM2 = (16 * 512 + 64 * 129 + 16 * 64 + 32) * 4;
    cudaFuncSetAttribute(bias_fused_mma, cudaFuncAttributeMaxDynamicSharedMemorySize, SM_TOT);
    cudaFuncSetAttribute(qknew_kernel,   cudaFuncAttributeMaxDynamicSharedMemorySize, SMEM2);

    prep_split<<<128, 256>>>(Wb, Wbo);
    proj_kernel<<<dim3(N_TOK, 2), 256>>>(q, Wq, bq, k, Wk, bk);

    bias_fused_mma<<<NN / 128, 512, SM_TOT>>>(bias, bb, bbo, out_bias);

    logits_kernel<<<dim3(N_TOK / 16, H_HEADS, 8), 256>>>();
    softmax_v_kernel<<<H_HEADS * N_TOK, 256>>>(v);
    mean_kernel<<<1, N_TOK>>>(out_vals);
    qknew_kernel<<<dim3(N_TOK / 16, 2), 256, SMEM2>>>(
        q, k, Wqo, bqo, Wko, bko, qg, qb, kg, kb, out);
}

// round 17
// speedup vs baseline: 5.8211x; 1.2221x over previous
#include <cuda_runtime.h>
#include <cuda_bf16.h>
#include <cuda_fp16.h>
#include <math.h>
#include <stdint.h>

// ---- problem constants ----
#define N_TOK   512
#define QDIM    64
#define H_HEADS 4
#define D_HEAD  128
#define HD      512
#define BD      128
#define HBD     512
#define NN      (N_TOK * N_TOK)
#define INV_SQRT_D 0.08838834764831845f

// ---- scratch globals ----
__device__ float g_pq[N_TOK * HD];
__device__ float g_pk[N_TOK * HD];
__device__ float g_diffs[H_HEADS * NN];
__device__ float g_logits[H_HEADS * NN];
__device__ float g_val[H_HEADS * N_TOK];
// weights pre-converted to fp16 MMA B-fragment order: [nc][8192] u32
__device__ uint32_t g_Wbf[H_HEADS * 8192];
__device__ uint32_t g_Wbof[H_HEADS * 8192];

// fast mish: mish(x) = x * tanh(softplus(x)) = x * u/(u+2), u = e^x(e^x+2)
__device__ __forceinline__ float mishf(float x) {
    float xc = fminf(x, 15.f);
    float e = __expf(xc);
    float u = e * (e + 2.f);
    return x * (u / (u + 2.f));
}
static __device__ __forceinline__ uint32_t pk2h(__half a, __half b) {
    return (uint32_t)__half_as_ushort(a) | ((uint32_t)__half_as_ushort(b) << 16);
}

// warp-level fp16 MMA (sm_80+ PTX; works on bare sm_103 target)
static __device__ __forceinline__ void mma16816(float* d, const uint32_t* a,
                                                uint32_t b0, uint32_t b1) {
    asm volatile(
        "mma.sync.aligned.m16n8k16.row.col.f32.f16.f16.f32 "
        "{%0,%1,%2,%3}, {%4,%5,%6,%7}, {%8,%9}, {%0,%1,%2,%3};"
        : "+f"(d[0]), "+f"(d[1]), "+f"(d[2]), "+f"(d[3])
        : "r"(a[0]), "r"(a[1]), "r"(a[2]), "r"(a[3]), "r"(b0), "r"(b1));
}

// B-frag u32 index for element (n, k) within a 128x128 chunk; range 0..8191
static __device__ __forceinline__ int bfrag_idx(int n, int k) {
    return (((n >> 3) * 8 + (k >> 4)) * 2 + ((k >> 3) & 1)) * 32 + (n & 7) * 4 + ((k & 7) >> 1);
}

// smem layout (bytes)
#define SMA      0          // A frags (fp16)       32 KB
#define SMWB     32768      // Wb frags             32 KB
#define SMWO     65536      // Wbo frags            32 KB
#define SMP      98304      // P frags (fp16)       32 KB
#define SM_BB    131072
#define SM_BBO   133120
#define SM_PART  133632
#define SM_TOT   134656

// =====================================================================
// Kernel 0: pre-convert Wb / Wbo to fp16 fragment order (chunk stride 8192)
// =====================================================================
__global__ void __launch_bounds__(256) prep_split(const float* __restrict__ Wb,
                                                  const float* __restrict__ Wbo)
{
    int i = blockIdx.x * 256 + threadIdx.x;   // 0..32767
    {
        // Wb[R (0..511)][k (0..127)] ; chunk nc = R>>7, n = R&127
        int R = i >> 6, k = (i & 63) * 2;
        int nc = R >> 7, n = R & 127;
        float w0 = Wb[R * 128 + k], w1 = Wb[R * 128 + k + 1];
        g_Wbf[nc * 8192 + bfrag_idx(n, k)] = pk2h(__float2half(w0), __float2half(w1));
    }
    {
        // Wbo[o (0..127)][col (0..511)] ; chunk nc = col>>7 ; n = o, k = col&127
        int nc = i >> 13, rem = i & 8191;
        int o = rem >> 6, jj = (rem & 63) * 2;
        float w0 = Wbo[o * 512 + nc * 128 + jj], w1 = Wbo[o * 512 + nc * 128 + jj + 1];
        g_Wbof[nc * 8192 + bfrag_idx(o, jj)] = pk2h(__float2half(w0), __float2half(w1));
    }
}

// =====================================================================
// Kernel 1: q/k projections
// =====================================================================
__global__ void __launch_bounds__(256) proj_kernel(
    const float* __restrict__ q,  const float* __restrict__ Wq, const float* __restrict__ bq,
    const float* __restrict__ k,  const float* __restrict__ Wk, const float* __restrict__ bk)
{
    const float* x; const float* W; const float* b; float* out;
    if (blockIdx.y == 0) { x = q; W = Wq; b = bq; out = g_pq; }
    else                 { x = k; W = Wk; b = bk; out = g_pk; }
    int n = blockIdx.x;
    int t = threadIdx.x;
    __shared__ float xs[QDIM];
    if (t < QDIM/4) ((float4*)xs)[t] = ((const float4*)(x + n * QDIM))[t];
    __syncthreads();
    for (int j = t; j < HD; j += 256) {
        float s = b[j];
        const float4* wr = (const float4*)(W + j * QDIM);
        #pragma unroll
        for (int c = 0; c < QDIM/4; c++) {
            float4 w = wr[c];
            s += xs[4*c+0]*w.x + xs[4*c+1]*w.y + xs[4*c+2]*w.z + xs[4*c+3]*w.w;
        }
        out[n * HD + j] = s;
    }
}

// =====================================================================
// Kernel 2: fused bias pipeline — FP16x1 both GEMMs.
// 512 threads, 16 warps. Warp (m = w&7, nh = w>>3):
//   rows 16m..16m+15, output cols nh*64..+63.
// =====================================================================
__global__ void __launch_bounds__(512, 1) bias_fused_mma(
    const float* __restrict__ bias, const float* __restrict__ bb,
    const float* __restrict__ bbo,  float* __restrict__ bias_out)
{
    extern __shared__ char smc[];
    uint32_t* Af  = (uint32_t*)(smc + SMA);
    uint32_t* Wbf = (uint32_t*)(smc + SMWB);
    uint32_t* Wof = (uint32_t*)(smc + SMWO);
    uint32_t* Pf  = (uint32_t*)(smc + SMP);
    float*    bb_s  = (float*)(smc + SM_BB);
    float*    bbo_s = (float*)(smc + SM_BBO);
    float*    part  = (float*)(smc + SM_PART);

    int t = threadIdx.x, wid = t >> 5, lane = t & 31;
    int gq = lane >> 2, tt = lane & 3;
    int m  = wid & 7;
    int nh = wid >> 3;
    int m0 = blockIdx.x * 128;

    if (t < 128) bbo_s[t] = bbo[t];
    if (t < 512) bb_s[t] = bb[t];

    // ---- stage bias tile -> A frag buffer (fp16) ----
    {
        const float4* src = (const float4*)(bias + (size_t)m0 * BD);
        #pragma unroll
        for (int i = t; i < 4096; i += 512) {
            int r = i >> 5, c = (i & 31) << 2;
            float4 v = src[i];
            int mt = r >> 4, g = r & 15, ks = c >> 4, cl = c & 15;
            int reg = ((cl >= 8) ? 2 : 0) + ((g >= 8) ? 1 : 0);
            int ln0 = (g & 7) * 4 + ((cl & 7) >> 1);
            int idx = ((mt * 8 + ks) * 4 + reg) * 32 + ln0;
            *(uint2*)(Af + idx) = make_uint2(
                pk2h(__float2half(v.x), __float2half(v.y)),
                pk2h(__float2half(v.z), __float2half(v.w)));
        }
    }

    float O[8][4];
    #pragma unroll
    for (int j = 0; j < 8; j++)
        #pragma unroll
        for (int r = 0; r < 4; r++) O[j][r] = 0.f;

    for (int nc = 0; nc < 4; nc++) {
        __syncthreads();
        // ---- stage Wb + Wbo chunks (2048 uint4 each = full 32 KB) ----
        {
            const uint4* sb = (const uint4*)(g_Wbf + nc * 8192);
            const uint4* so = (const uint4*)(g_Wbof + nc * 8192);
            #pragma unroll
            for (int i = t; i < 2048; i += 512) {
                ((uint4*)Wbf)[i] = sb[i];
                ((uint4*)Wof)[i] = so[i];
            }
        }
        __syncthreads();

        // ---- GEMM1: D1 = A @ Wb^T (1-pass fp16) ----
        float D1[8][4];
        #pragma unroll
        for (int j = 0; j < 8; j++)
            #pragma unroll
            for (int r = 0; r < 4; r++) D1[j][r] = 0.f;

        #pragma unroll
        for (int ks = 0; ks < 8; ks++) {
            uint32_t a[4];
            int ab = (m * 8 + ks) * 128;
            #pragma unroll
            for (int r = 0; r < 4; r++) a[r] = Af[ab + r * 32 + lane];
            #pragma unroll
            for (int j = 0; j < 8; j++) {
                int jt = nh * 8 + j;
                int wb = ((jt * 8 + ks) * 2) * 32 + lane;
                mma16816(D1[j], a, Wbf[wb], Wbf[wb + 32]);
            }
        }

        // ---- convert: P = D1 + bb -> fp16 -> SMEM P frags; norms (fp32) ----
        float sqlo = 0.f, sqhi = 0.f;
        #pragma unroll
        for (int j = 0; j < 8; j++) {
            int jt = nh * 8 + j;
            float b0 = bb_s[nc * 128 + jt * 8 + 2 * tt];
            float b1 = bb_s[nc * 128 + jt * 8 + 2 * tt + 1];
            float p0 = D1[j][0] + b0, p1 = D1[j][1] + b1;
            float p2 = D1[j][2] + b0, p3 = D1[j][3] + b1;
            sqlo += p0 * p0 + p1 * p1;
            sqhi += p2 * p2 + p3 * p3;
            int s = jt >> 1, hi8 = jt & 1;
            int i0 = ((m * 8 + s) * 4 + hi8 * 2) * 32 + lane;
            Pf[i0]      = pk2h(__float2half(p0), __float2half(p1));
            Pf[i0 + 32] = pk2h(__float2half(p2), __float2half(p3));
        }
        sqlo += __shfl_xor_sync(0xFFFFFFFF, sqlo, 1);
        sqlo += __shfl_xor_sync(0xFFFFFFFF, sqlo, 2);
        sqhi += __shfl_xor_sync(0xFFFFFFFF, sqhi, 1);
        sqhi += __shfl_xor_sync(0xFFFFFFFF, sqhi, 2);
        if (tt == 0) {
            part[nh * 128 + m * 16 + gq]     = sqlo;
            part[nh * 128 + m * 16 + gq + 8] = sqhi;
        }

        __syncthreads();

        if (t < 128)
            g_diffs[(size_t)nc * NN + m0 + t] = sqrtf(part[t] + part[128 + t]);

        // ---- GEMM2: O += P @ Wbo^T (1-pass fp16) ----
        #pragma unroll
        for (int ks = 0; ks < 8; ks++) {
            uint32_t p[4];
            int pb = (m * 8 + ks) * 128;
            #pragma unroll
            for (int r = 0; r < 4; r++) p[r] = Pf[pb + r * 32 + lane];
            #pragma unroll
            for (int j = 0; j < 8; j++) {
                int jt = nh * 8 + j;
                int wb = ((jt * 8 + ks) * 2) * 32 + lane;
                mma16816(O[j], p, Wof[wb], Wof[wb + 32]);
            }
        }
    }

    // ---- final: O + bbo, mish -> gmem ----
    int row = m0 + m * 16 + gq;
    #pragma unroll
    for (int j = 0; j < 8; j++) {
        int col = nh * 64 + j * 8 + 2 * tt;
        float b0 = bbo_s[col], b1 = bbo_s[col + 1];
        float2 v0, v1;
        v0.x = mishf(O[j][0] + b0);  v0.y = mishf(O[j][1] + b1);
        v1.x = mishf(O[j][2] + b0);  v1.y = mishf(O[j][3] + b1);
        *(float2*)(bias_out + (size_t)row * BD + col)       = v0;
        *(float2*)(bias_out + (size_t)(row + 8) * BD + col) = v1;
    }
}

// =====================================================================
// Kernel 3: logits — 32-k chunks (grid (32, 4, 16)), ~25 KB smem for
// higher occupancy. Thread: 1 q row x 2 k columns.
// =====================================================================
__global__ void __launch_bounds__(256) logits_kernel()
{
    __shared__ float pq_s[16 * 128];
    __shared__ float pk_s[32 * 129];
    int q0 = blockIdx.x * 16;
    int h  = blockIdx.y;
    int kc = blockIdx.z;
    int t  = threadIdx.x;
    int qi = t >> 4;
    int kx = t & 15;

    #pragma unroll
    for (int i = t; i < 16 * 32; i += 256) {
        int r = i >> 5, c4 = i & 31;
        ((float4*)pq_s)[r * 32 + c4] = ((const float4*)g_pq)[(q0 + r) * 128 + h * 32 + c4];
    }
    #pragma unroll
    for (int i = t; i < 32 * 32; i += 256) {
        int r = i >> 5, c4 = i & 31;
        float4 w = ((const float4*)g_pk)[(kc * 32 + r) * 128 + h * 32 + c4];
        float* dst = pk_s + r * 129 + c4 * 4;
        dst[0] = w.x; dst[1] = w.y; dst[2] = w.z; dst[3] = w.w;
    }
    __syncthreads();

    float acc0 = 0, acc1 = 0;
    const float* ap = pq_s + qi * 128;
    const float* k0 = pk_s + (kx * 2    ) * 129;
    const float* k1 = pk_s + (kx * 2 + 1) * 129;
    #pragma unroll 8
    for (int d = 0; d < 128; d++) {
        float a = ap[d];
        acc0 += a * k0[d]; acc1 += a * k1[d];
    }
    size_t base = (size_t)h * NN + (size_t)(q0 + qi) * N_TOK + kc * 32 + kx * 2;
    float2 dsum = *(const float2*)(g_diffs + base);
    float2 o;
    o.x = acc0 * INV_SQRT_D + dsum.x;
    o.y = acc1 * INV_SQRT_D + dsum.y;
    *(float2*)(g_logits + base) = o;
}

// =====================================================================
// Kernel 4: softmax + v
// =====================================================================
__global__ void __launch_bounds__(256) softmax_v_kernel(const float* __restrict__ v)
{
    __shared__ float r1[256];
    __shared__ float r2[256];
    int hq = blockIdx.x;
    int t  = threadIdx.x;
    const float* lr = g_logits + (size_t)hq * N_TOK;
    float l0 = lr[t], l1 = lr[t + 256];
    float m = fmaxf(l0, l1);
    r1[t] = m;
    __syncthreads();
    #pragma unroll
    for (int s = 128; s > 0; s >>= 1) {
        if (t < s) r1[t] = fmaxf(r1[t], r1[t + s]);
        __syncthreads();
    }
    m = r1[0];
    __syncthreads();
    float e0 = expf(l0 - m), e1 = expf(l1 - m);
    r1[t] = e0 + e1;
    r2[t] = e0 * v[t] + e1 * v[t + 256];
    __syncthreads();
    #pragma unroll
    for (int s = 128; s > 0; s >>= 1) {
        if (t < s) { r1[t] += r1[t + s]; r2[t] += r2[t + s]; }
        __syncthreads();
    }
    if (t == 0) g_val[hq] = r2[0] / r1[0];
}

__global__ void mean_kernel(float* __restrict__ out)
{
    int t = threadIdx.x;
    out[t] = 0.25f * (g_val[t] + g_val[N_TOK + t] + g_val[2 * N_TOK + t] + g_val[3 * N_TOK + t]);
}

// =====================================================================
// Kernel 6: q_new / k_new heads
// =====================================================================
__global__ void __launch_bounds__(256) qknew_kernel(
    const float* __restrict__ qin, const float* __restrict__ kin,
    const float* __restrict__ Wqo, const float* __restrict__ bqo,
    const float* __restrict__ Wko, const float* __restrict__ bko,
    const float* __restrict__ qg,  const float* __restrict__ qb,
    const float* __restrict__ kg,  const float* __restrict__ kb,
    float* __restrict__ out)
{
    extern __shared__ float sm[];
    float* s_flat = sm;
    float* Wsm    = sm + 16 * 512;
    float* zs     = Wsm + 64 * 129;
    float* mn     = zs + 16 * 64;
    float* rs     = mn + 16;

    const float* proj; const float* W; const float* bo; const float* xin;
    const float* g; const float* bt; float* o;
    if (blockIdx.y == 0) { proj = g_pq; W = Wqo; bo = bqo; xin = qin; g = qg; bt = qb; o = out; }
    else                 { proj = g_pk; W = Wko; bo = bko; xin = kin; g = kg; bt = kb; o = out + N_TOK * QDIM; }

    int n0 = blockIdx.x * 16;
    int t  = threadIdx.x;
    int oi = t & 63;
    int rseg = t >> 6;

    #pragma unroll
    for (int i = t; i < 16 * 128; i += 256)
        ((float4*)s_flat)[i] = ((const float4*)proj)[n0 * 128 + i];
    __syncthreads();

    float acc[4] = {0.f, 0.f, 0.f, 0.f};
    for (int jc = 0; jc < 4; jc++) {
        __syncthreads();
        #pragma unroll
        for (int i = t; i < 64 * 32; i += 256) {
            int oo = i >> 5, c4 = i & 31;
            float4 w = ((const float4*)W)[oo * 128 + jc * 32 + c4];
            float* dst = Wsm + oo * 129 + c4 * 4;
            dst[0] = w.x; dst[1] = w.y; dst[2] = w.z; dst[3] = w.w;
        }
        __syncthreads();
        #pragma unroll 4
        for (int jj = 0; jj < 128; jj++) {
            int j = jc * 128 + jj;
            int pidx = (j & 3) * 128 + (j >> 2);
            float w = Wsm[oi * 129 + jj];
            #pragma unroll
            for (int i = 0; i < 4; i++)
                acc[i] += s_flat[(rseg * 4 + i) * 512 + pidx] * w;
        }
    }

    #pragma unroll
    for (int i = 0; i < 4; i++) {
        int r = rseg * 4 + i;
        float x = acc[i] + bo[oi];
        zs[r * 64 + oi] = xin[(n0 + r) * QDIM + oi] + mishf(x);
    }
    __syncthreads();
    if (t < 16) {
        float s = 0.f;
        for (int c = 0; c < 64; c++) s += zs[t * 64 + c];
        float mean = s * (1.f / 64.f);
        float v2 = 0.f;
        for (int c = 0; c < 64; c++) { float d = zs[t * 64 + c] - mean; v2 += d * d; }
        mn[t] = mean;
        rs[t] = rsqrtf(v2 * (1.f / 64.f) + 1e-5f);
    }
    __syncthreads();
    #pragma unroll
    for (int i = 0; i < 4; i++) {
        int r = rseg * 4 + i;
        float zz = zs[r * 64 + oi];
        o[(n0 + r) * QDIM + oi] = (zz - mn[r]) * rs[r] * g[oi] + bt[oi];
    }
}

// =====================================================================
// launch
// =====================================================================
extern "C" void kernel_launch(void* const* d_in, const int* in_sizes, int n_in,
                              void* d_out, int out_size)
{
    const float* q    = (const float*)d_in[0];
    const float* k    = (const float*)d_in[1];
    const float* v    = (const float*)d_in[2];
    const float* bias = (const float*)d_in[3];
    const float* Wq   = (const float*)d_in[4];
    const float* bq   = (const float*)d_in[5];
    const float* Wk   = (const float*)d_in[6];
    const float* bk   = (const float*)d_in[7];
    const float* Wqo  = (const float*)d_in[8];
    const float* bqo  = (const float*)d_in[9];
    const float* Wko  = (const float*)d_in[10];
    const float* bko  = (const float*)d_in[11];
    const float* qg   = (const float*)d_in[12];
    const float* qb   = (const float*)d_in[13];
    const float* kg   = (const float*)d_in[14];
    const float* kb   = (const float*)d_in[15];
    const float* Wb   = (const float*)d_in[16];
    const float* bb   = (const float*)d_in[17];
    const float* Wbo  = (const float*)d_in[18];
    const float* bbo  = (const float*)d_in[19];

    float* out       = (float*)d_out;
    float* out_vals  = out + 2 * N_TOK * QDIM;
    float* out_bias  = out_vals + N_TOK;

    const int SMEM2 = (16 * 512 + 64 * 129 + 16 * 64 + 32) * 4;
    cudaFuncSetAttribute(bias_fused_mma, cudaFuncAttributeMaxDynamicSharedMemorySize, SM_TOT);
    cudaFuncSetAttribute(qknew_kernel,   cudaFuncAttributeMaxDynamicSharedMemorySize, SMEM2);

    prep_split<<<128, 256>>>(Wb, Wbo);
    proj_kernel<<<dim3(N_TOK, 2), 256>>>(q, Wq, bq, k, Wk, bk);

    bias_fused_mma<<<NN / 128, 512, SM_TOT>>>(bias, bb, bbo, out_bias);

    logits_kernel<<<dim3(N_TOK / 16, H_HEADS, 16), 256>>>();
    softmax_v_kernel<<<H_HEADS * N_TOK, 256>>>(v);
    mean_kernel<<<1, N_TOK>>>(out_vals);
    qknew_kernel<<<dim3(N_TOK / 16, 2), 256, SMEM2>>>(
        q, k, Wqo, bqo, Wko, bko, qg, qb, kg, kb, out);
}